// round 1
// baseline (speedup 1.0000x reference)
#include <cuda_runtime.h>
#include <math.h>

#define DEPTH  6
#define DIM    512
#define HEADS  8
#define DH     64
#define NB     266
#define FFD    2048
#define OUTD   32
#define BATCH  4
#define SEQ    8192
#define MROWS  (BATCH*SEQ)   // 32768
#define BH     (BATCH*HEADS) // 32
#define MPAD   320           // NB padded to 5*64
#define PSTR   65            // proj smem row stride (conflict-free)
#define QSTR   65            // q-tile smem row stride
#define QPSTR  272           // qp smem row stride
#define EPSF   1e-4f
#define DN     0.3535533905932738f     // 64^-0.25
#define RATIO  0.06131393394849658f    // 266^-0.5
#define SPLITK 4

// ---------------- scratch (static device memory; no runtime allocation) ----------------
__device__ float g_x[MROWS*DIM];
__device__ float g_h[MROWS*DIM];
__device__ float g_q[MROWS*DIM];
__device__ float g_k[MROWS*DIM];
__device__ float g_v[MROWS*DIM];
__device__ float g_o[MROWS*DIM];
__device__ float g_ff[MROWS*FFD];
__device__ float g_kp[BH*SEQ*MPAD];      // 83,886,080 floats
__device__ float g_ctx[BH*MPAD*DH];
__device__ float g_ksum[BH*MPAD];
__device__ float g_kmax;

// ---------------- helpers ----------------
__device__ __forceinline__ void atomicMaxF(float* addr, float val) {
    int old = __float_as_int(*addr);
    while (__int_as_float(old) < val) {
        int assumed = old;
        old = atomicCAS((int*)addr, assumed, __float_as_int(val));
        if (old == assumed) break;
    }
}

__device__ __forceinline__ float gelu_tanh(float x) {
    float x3 = x * x * x;
    return 0.5f * x * (1.0f + tanhf(0.7978845608028654f * (x + 0.044715f * x3)));
}

// ---------------- init / reset ----------------
__global__ void copy_src_kernel(const float* __restrict__ src) {
    int i = blockIdx.x * blockDim.x + threadIdx.x;
    if (i < MROWS*DIM) g_x[i] = src[i];
}

__global__ void reset_kernel() {
    int i = blockIdx.x * blockDim.x + threadIdx.x;
    if (i < BH*MPAD*DH) g_ctx[i] = 0.f;
    if (i < BH*MPAD)    g_ksum[i] = 0.f;
    if (i == 0)         g_kmax = __int_as_float(0xff800000); // -inf
}

// ---------------- LayerNorm (one row per block, 128 threads) ----------------
__global__ void __launch_bounds__(128) ln_kernel(
    const float* __restrict__ x, const float* __restrict__ g,
    const float* __restrict__ b, float* __restrict__ o)
{
    int row = blockIdx.x, tid = threadIdx.x, lane = tid & 31, w = tid >> 5;
    const float4 xv = ((const float4*)(x + (size_t)row*DIM))[tid];
    float s = xv.x + xv.y + xv.z + xv.w;
    float q = xv.x*xv.x + xv.y*xv.y + xv.z*xv.z + xv.w*xv.w;
    #pragma unroll
    for (int off = 16; off; off >>= 1) {
        s += __shfl_xor_sync(0xffffffffu, s, off);
        q += __shfl_xor_sync(0xffffffffu, q, off);
    }
    __shared__ float ss[4], sq[4];
    if (lane == 0) { ss[w] = s; sq[w] = q; }
    __syncthreads();
    float S = ss[0]+ss[1]+ss[2]+ss[3];
    float Q = sq[0]+sq[1]+sq[2]+sq[3];
    float mean = S * (1.0f/DIM);
    float var  = Q * (1.0f/DIM) - mean*mean;
    float inv  = rsqrtf(var + 1e-5f);
    float4 gv = ((const float4*)g)[tid];
    float4 bv = ((const float4*)b)[tid];
    float4 ov;
    ov.x = (xv.x - mean)*inv*gv.x + bv.x;
    ov.y = (xv.y - mean)*inv*gv.y + bv.y;
    ov.z = (xv.z - mean)*inv*gv.z + bv.z;
    ov.w = (xv.w - mean)*inv*gv.w + bv.w;
    ((float4*)(o + (size_t)row*DIM))[tid] = ov;
}

// ---------------- SIMT SGEMM: C = [res +] epilogue(A[M,K] * W[K,N] [+ bias]) ----------------
// BM=BN=128, BK=8, 256 threads, 8x8 per thread. M%128==0, N%128==0, K%8==0.
template<int BIASF, int RESF, int GELUF>
__global__ void __launch_bounds__(256) gemm_kernel(
    const float* __restrict__ A, const float* __restrict__ W,
    const float* __restrict__ bias, const float* __restrict__ res,
    float* __restrict__ C, int M, int N, int K)
{
    __shared__ float As[8][128];
    __shared__ float Ws[8][128];
    int bx = blockIdx.x, by = blockIdx.y, tid = threadIdx.x;
    int arow = tid >> 1, acol = (tid & 1) * 4;
    int wrow = tid >> 5, wcol = (tid & 31) * 4;
    int tx = tid & 15, ty = tid >> 4;
    const float* Ab = A + (size_t)(by*128) * K;
    const float* Wb = W + bx*128;
    float acc[8][8];
    #pragma unroll
    for (int i = 0; i < 8; i++)
        #pragma unroll
        for (int j = 0; j < 8; j++) acc[i][j] = 0.f;

    for (int k0 = 0; k0 < K; k0 += 8) {
        float4 av = *(const float4*)(Ab + (size_t)arow*K + k0 + acol);
        As[acol+0][arow] = av.x; As[acol+1][arow] = av.y;
        As[acol+2][arow] = av.z; As[acol+3][arow] = av.w;
        *(float4*)&Ws[wrow][wcol] = *(const float4*)(Wb + (size_t)(k0 + wrow)*N + wcol);
        __syncthreads();
        #pragma unroll
        for (int kk = 0; kk < 8; kk++) {
            float4 a0 = *(float4*)&As[kk][ty*8];
            float4 a1 = *(float4*)&As[kk][ty*8+4];
            float4 b0 = *(float4*)&Ws[kk][tx*8];
            float4 b1 = *(float4*)&Ws[kk][tx*8+4];
            float av_[8] = {a0.x,a0.y,a0.z,a0.w,a1.x,a1.y,a1.z,a1.w};
            float bv_[8] = {b0.x,b0.y,b0.z,b0.w,b1.x,b1.y,b1.z,b1.w};
            #pragma unroll
            for (int i = 0; i < 8; i++)
                #pragma unroll
                for (int j = 0; j < 8; j++)
                    acc[i][j] += av_[i]*bv_[j];
        }
        __syncthreads();
    }
    int rowb = by*128 + ty*8;
    int colb = bx*128 + tx*8;
    #pragma unroll
    for (int i = 0; i < 8; i++) {
        float* crow = C + (size_t)(rowb+i)*N + colb;
        const float* rrow = RESF ? (res + (size_t)(rowb+i)*N + colb) : (const float*)0;
        #pragma unroll
        for (int j = 0; j < 8; j++) {
            float v = acc[i][j];
            if (BIASF) v += bias[colb+j];
            if (GELUF) v = gelu_tanh(v);
            if (RESF)  v += rrow[j];
            crow[j] = v;
        }
    }
}

// ---------------- Attention feature kernels ----------------
// MODE 0: global max of xp(k)  -> g_kmax (atomicMax)
// MODE 1: kp = ratio*(exp(xp - diag - kmax)+eps) -> g_kp (zero-padded to MPAD)
// MODE 2: qp per-row-max fused with  o = (qp*ctx)/(qp*ksum) -> g_o
// Block: 256 threads (8 warps x 4 rows), 32 rows of one (b,h) per block.
template<int MODE>
__global__ void __launch_bounds__(256) attn_kernel(const float* __restrict__ proj)
{
    extern __shared__ float sm[];
    float* projs = sm;                          // NB*PSTR   = 17290
    float* qs    = projs + NB*PSTR;             // 32*QSTR   = 2080
    float* diag  = qs + 32*QSTR;                // 32
    float* ctxs  = diag + 32;                   // NB*DH     = 17024 (MODE2)
    float* ksums = ctxs + NB*DH;                // 272       (MODE2)
    float* qps   = ksums + 272;                 // 32*QPSTR  = 8704  (MODE2)

    const int tid = threadIdx.x, lane = tid & 31, w = tid >> 5;
    const int bh = blockIdx.y, b = bh >> 3, hh = bh & 7;
    const int n0 = blockIdx.x * 32;
    const float* inp = (MODE == 2) ? g_q : g_k;
    const float* src = inp + ((size_t)b*SEQ + n0)*DIM + hh*DH;

    for (int i = tid; i < NB*DH; i += 256)
        projs[(i>>6)*PSTR + (i&63)] = proj[i];
    for (int i = tid; i < 32*DH; i += 256)
        qs[(i>>6)*QSTR + (i&63)] = src[(size_t)(i>>6)*DIM + (i&63)] * DN;
    if (MODE == 2) {
        const float* cb = g_ctx + (size_t)bh*MPAD*DH;
        for (int i = tid; i < NB*DH; i += 256) ctxs[i] = cb[i];
        const float* kb = g_ksum + (size_t)bh*MPAD;
        for (int i = tid; i < NB; i += 256) ksums[i] = kb[i];
    }
    __syncthreads();
    if (MODE != 0 && tid < 32) {
        float s = 0.f;
        const float* qr = &qs[tid*QSTR];
        #pragma unroll 16
        for (int d = 0; d < DH; d++) s += qr[d]*qr[d];
        diag[tid] = 0.5f * s;
    }
    __syncthreads();

    const int r0 = w * 4;
    float acc[9][4];
    #pragma unroll
    for (int t = 0; t < 9; t++)
        #pragma unroll
        for (int r = 0; r < 4; r++) acc[t][r] = 0.f;

    // xp tile: 4 rows per warp x 9 features per lane (j = lane + 32t)
    for (int d0 = 0; d0 < DH; d0 += 8) {
        float qreg[4][8];
        #pragma unroll
        for (int r = 0; r < 4; r++)
            #pragma unroll
            for (int dd = 0; dd < 8; dd++)
                qreg[r][dd] = qs[(r0+r)*QSTR + d0 + dd];
        #pragma unroll
        for (int t = 0; t < 9; t++) {
            int j = lane + 32*t;
            if (j < NB) {
                const float* pr = &projs[j*PSTR + d0];
                #pragma unroll
                for (int dd = 0; dd < 8; dd++) {
                    float p = pr[dd];
                    acc[t][0] += qreg[0][dd]*p;
                    acc[t][1] += qreg[1][dd]*p;
                    acc[t][2] += qreg[2][dd]*p;
                    acc[t][3] += qreg[3][dd]*p;
                }
            }
        }
    }

    if (MODE == 0) {
        float m = __int_as_float(0xff800000);
        #pragma unroll
        for (int t = 0; t < 9; t++) {
            int j = lane + 32*t;
            if (j < NB) {
                #pragma unroll
                for (int r = 0; r < 4; r++) m = fmaxf(m, acc[t][r]);
            }
        }
        #pragma unroll
        for (int off = 16; off; off >>= 1) m = fmaxf(m, __shfl_xor_sync(0xffffffffu, m, off));
        __shared__ float wm[8];
        if (lane == 0) wm[w] = m;
        __syncthreads();
        if (tid == 0) {
            float mm = wm[0];
            #pragma unroll
            for (int i = 1; i < 8; i++) mm = fmaxf(mm, wm[i]);
            atomicMaxF(&g_kmax, mm);
        }
        return;
    }

    if (MODE == 1) {
        float km = g_kmax;
        #pragma unroll
        for (int r = 0; r < 4; r++) {
            int rr = r0 + r;
            float dg = diag[rr];
            float* orow = g_kp + ((size_t)bh*SEQ + n0 + rr)*MPAD;
            #pragma unroll
            for (int t = 0; t < 9; t++) {
                int j = lane + 32*t;
                if (j < NB) orow[j] = RATIO * (expf(acc[t][r] - dg - km) + EPSF);
            }
            for (int mz = NB + lane; mz < MPAD; mz += 32) orow[mz] = 0.f;
        }
        return;
    }

    // MODE 2: per-row max, qp to smem, then o = qp*ctx / (qp*ksum)
    #pragma unroll
    for (int r = 0; r < 4; r++) {
        int rr = r0 + r;
        float m = __int_as_float(0xff800000);
        #pragma unroll
        for (int t = 0; t < 9; t++) {
            int j = lane + 32*t;
            if (j < NB) m = fmaxf(m, acc[t][r]);
        }
        #pragma unroll
        for (int off = 16; off; off >>= 1) m = fmaxf(m, __shfl_xor_sync(0xffffffffu, m, off));
        float dg = diag[rr];
        float* qrow = &qps[rr*QPSTR];
        #pragma unroll
        for (int t = 0; t < 9; t++) {
            int j = lane + 32*t;
            if (j < NB) qrow[j] = RATIO * (expf(acc[t][r] - dg - m) + EPSF);
        }
    }
    __syncwarp();

    float ov[4][2];
    #pragma unroll
    for (int r = 0; r < 4; r++) { ov[r][0] = 0.f; ov[r][1] = 0.f; }
    #pragma unroll 2
    for (int m = 0; m < NB; m++) {
        float2 c = *(const float2*)&ctxs[m*DH + 2*lane];
        #pragma unroll
        for (int r = 0; r < 4; r++) {
            float p = qps[(r0+r)*QPSTR + m];
            ov[r][0] += p * c.x;
            ov[r][1] += p * c.y;
        }
    }
    float dnm[4] = {0.f, 0.f, 0.f, 0.f};
    for (int m = lane; m < NB; m += 32) {
        float s = ksums[m];
        dnm[0] += qps[(r0+0)*QPSTR + m]*s;
        dnm[1] += qps[(r0+1)*QPSTR + m]*s;
        dnm[2] += qps[(r0+2)*QPSTR + m]*s;
        dnm[3] += qps[(r0+3)*QPSTR + m]*s;
    }
    #pragma unroll
    for (int off = 16; off; off >>= 1) {
        dnm[0] += __shfl_xor_sync(0xffffffffu, dnm[0], off);
        dnm[1] += __shfl_xor_sync(0xffffffffu, dnm[1], off);
        dnm[2] += __shfl_xor_sync(0xffffffffu, dnm[2], off);
        dnm[3] += __shfl_xor_sync(0xffffffffu, dnm[3], off);
    }
    #pragma unroll
    for (int r = 0; r < 4; r++) {
        int rr = r0 + r;
        float inv = 1.0f / dnm[r];
        float* orow = g_o + ((size_t)b*SEQ + n0 + rr)*DIM + hh*DH;
        float2 res2;
        res2.x = ov[r][0] * inv;
        res2.y = ov[r][1] * inv;
        *(float2*)&orow[2*lane] = res2;
    }
}

// ---------------- ctx[bh,m,d] = sum_n kp[bh,n,m]*v[bh,n,d] (+ fused k_sum), split-K atomics ----
__global__ void __launch_bounds__(256) ctx_kernel()
{
    __shared__ float As[16][64];
    __shared__ float Bs[16][64];
    int tid = threadIdx.x;
    int m0 = blockIdx.x * 64;
    int bh = blockIdx.y, b = bh >> 3, hh = bh & 7;
    int nbase = blockIdx.z * (SEQ / SPLITK);
    int lrow = tid >> 4, lcol = (tid & 15) * 4;
    int tx = tid & 15, ty = tid >> 4;
    float acc[4][4];
    #pragma unroll
    for (int i = 0; i < 4; i++)
        #pragma unroll
        for (int j = 0; j < 4; j++) acc[i][j] = 0.f;
    float ks[4] = {0.f, 0.f, 0.f, 0.f};
    const float* kpb = g_kp + (size_t)bh*SEQ*MPAD + m0;
    const float* vb  = g_v + (size_t)b*SEQ*DIM + hh*DH;
    for (int k0 = 0; k0 < SEQ/SPLITK; k0 += 16) {
        int n = nbase + k0;
        *(float4*)&As[lrow][lcol] = *(const float4*)(kpb + (size_t)(n+lrow)*MPAD + lcol);
        *(float4*)&Bs[lrow][lcol] = *(const float4*)(vb  + (size_t)(n+lrow)*DIM  + lcol);
        __syncthreads();
        #pragma unroll
        for (int kk = 0; kk < 16; kk++) {
            float4 a = *(float4*)&As[kk][ty*4];
            float4 bv = *(float4*)&Bs[kk][tx*4];
            float av_[4] = {a.x, a.y, a.z, a.w};
            float bv_[4] = {bv.x, bv.y, bv.z, bv.w};
            #pragma unroll
            for (int i = 0; i < 4; i++)
                #pragma unroll
                for (int j = 0; j < 4; j++)
                    acc[i][j] += av_[i]*bv_[j];
            if (tx == 0) { ks[0]+=a.x; ks[1]+=a.y; ks[2]+=a.z; ks[3]+=a.w; }
        }
        __syncthreads();
    }
    float* cb = g_ctx + (size_t)bh*MPAD*DH;
    #pragma unroll
    for (int i = 0; i < 4; i++)
        #pragma unroll
        for (int j = 0; j < 4; j++)
            atomicAdd(&cb[(m0 + ty*4 + i)*DH + tx*4 + j], acc[i][j]);
    if (tx == 0) {
        #pragma unroll
        for (int i = 0; i < 4; i++)
            atomicAdd(&g_ksum[bh*MPAD + m0 + ty*4 + i], ks[i]);
    }
}

// ---------------- final fc: out[M,32] = x[M,512]*fc_w + fc_b ----------------
__global__ void __launch_bounds__(256) fc_kernel(
    const float* __restrict__ x, const float* __restrict__ w,
    const float* __restrict__ bias, float* __restrict__ out)
{
    __shared__ float xs[8*DIM];
    int tid = threadIdx.x;
    int m0 = blockIdx.x * 8;
    for (int i = tid; i < 8*DIM/4; i += 256)
        ((float4*)xs)[i] = ((const float4*)(x + (size_t)m0*DIM))[i];
    __syncthreads();
    int r = tid >> 5, c = tid & 31;
    float acc = 0.f;
    const float* xr = &xs[r*DIM];
    #pragma unroll 8
    for (int k = 0; k < DIM; k++) acc += xr[k] * w[k*OUTD + c];
    out[(size_t)(m0 + r)*OUTD + c] = acc + bias[c];
}

// ---------------- host launcher ----------------
extern "C" void kernel_launch(void* const* d_in, const int* in_sizes, int n_in,
                              void* d_out, int out_size)
{
    (void)in_sizes; (void)n_in; (void)out_size;
    const float* src  = (const float*)d_in[0];
    const float* proj = (const float*)d_in[1];
    const float* ln1g = (const float*)d_in[2];
    const float* ln1b = (const float*)d_in[3];
    const float* Wq   = (const float*)d_in[4];
    const float* Wk   = (const float*)d_in[5];
    const float* Wv   = (const float*)d_in[6];
    const float* Wo   = (const float*)d_in[7];
    const float* bo   = (const float*)d_in[8];
    const float* ln2g = (const float*)d_in[9];
    const float* ln2b = (const float*)d_in[10];
    const float* W1   = (const float*)d_in[11];
    const float* b1   = (const float*)d_in[12];
    const float* W2   = (const float*)d_in[13];
    const float* b2   = (const float*)d_in[14];
    const float* fcw  = (const float*)d_in[15];
    const float* fcb  = (const float*)d_in[16];
    float* out = (float*)d_out;

    float *xp, *hp, *qb, *kb, *vb, *ob, *ffb;
    cudaGetSymbolAddress((void**)&xp,  g_x);
    cudaGetSymbolAddress((void**)&hp,  g_h);
    cudaGetSymbolAddress((void**)&qb,  g_q);
    cudaGetSymbolAddress((void**)&kb,  g_k);
    cudaGetSymbolAddress((void**)&vb,  g_v);
    cudaGetSymbolAddress((void**)&ob,  g_o);
    cudaGetSymbolAddress((void**)&ffb, g_ff);

    const int smem01 = (NB*PSTR + 32*QSTR + 32) * 4;                              // 77608 B
    const int smem2  = (NB*PSTR + 32*QSTR + 32 + NB*DH + 272 + 32*QPSTR) * 4;     // 181608 B
    cudaFuncSetAttribute(attn_kernel<0>, cudaFuncAttributeMaxDynamicSharedMemorySize, smem01);
    cudaFuncSetAttribute(attn_kernel<1>, cudaFuncAttributeMaxDynamicSharedMemorySize, smem01);
    cudaFuncSetAttribute(attn_kernel<2>, cudaFuncAttributeMaxDynamicSharedMemorySize, smem2);

    copy_src_kernel<<<(MROWS*DIM + 255)/256, 256>>>(src);

    dim3 gg(DIM/128, MROWS/128);       // 4 x 256
    dim3 gf(FFD/128, MROWS/128);       // 16 x 256
    dim3 ag(SEQ/32, BH);               // 256 x 32

    for (int L = 0; L < DEPTH; L++) {
        const float* pj = proj + (size_t)L*NB*DH;
        ln_kernel<<<MROWS, 128>>>(xp, ln1g + L*DIM, ln1b + L*DIM, hp);
        gemm_kernel<0,0,0><<<gg, 256>>>(hp, Wq + (size_t)L*DIM*DIM, 0, 0, qb, MROWS, DIM, DIM);
        gemm_kernel<0,0,0><<<gg, 256>>>(hp, Wk + (size_t)L*DIM*DIM, 0, 0, kb, MROWS, DIM, DIM);
        gemm_kernel<0,0,0><<<gg, 256>>>(hp, Wv + (size_t)L*DIM*DIM, 0, 0, vb, MROWS, DIM, DIM);
        reset_kernel<<<(BH*MPAD*DH + 255)/256, 256>>>();
        attn_kernel<0><<<ag, 256, smem01>>>(pj);
        attn_kernel<1><<<ag, 256, smem01>>>(pj);
        ctx_kernel<<<dim3(MPAD/64, BH, SPLITK), 256>>>();
        attn_kernel<2><<<ag, 256, smem2>>>(pj);
        gemm_kernel<1,1,0><<<gg, 256>>>(ob, Wo + (size_t)L*DIM*DIM, bo + L*DIM, xp, xp, MROWS, DIM, DIM);
        ln_kernel<<<MROWS, 128>>>(xp, ln2g + L*DIM, ln2b + L*DIM, hp);
        gemm_kernel<1,0,1><<<gf, 256>>>(hp, W1 + (size_t)L*DIM*FFD, b1 + L*FFD, 0, ffb, MROWS, FFD, DIM);
        gemm_kernel<1,1,0><<<gg, 256>>>(ffb, W2 + (size_t)L*FFD*DIM, b2 + L*DIM, xp, xp, MROWS, DIM, FFD);
    }
    fc_kernel<<<MROWS/8, 256>>>(xp, fcw, fcb, out);
}

// round 2
// speedup vs baseline: 1.7766x; 1.7766x over previous
#include <cuda_runtime.h>
#include <math.h>

#define DEPTH  6
#define DIM    512
#define HEADS  8
#define DH     64
#define NB     266
#define FFD    2048
#define OUTD   32
#define BATCH  4
#define SEQ    8192
#define MROWS  (BATCH*SEQ)   // 32768
#define BH     (BATCH*HEADS) // 32
#define MPAD   320           // NB padded to 5*64
#define PSTR   65            // proj smem row stride (conflict-free)
#define QSTR   65            // q-tile smem row stride
#define QPSTR  272           // qp smem row stride
#define EPSF   1e-4f
#define DN     0.3535533905932738f     // 64^-0.25
#define RATIO  0.06131393394849658f    // 266^-0.5
#define SPLITK 4

// ---------------- scratch (static device memory; no runtime allocation) ----------------
__device__ float g_x[MROWS*DIM];
__device__ float g_h[MROWS*DIM];
__device__ float g_q[MROWS*DIM];
__device__ float g_k[MROWS*DIM];
__device__ float g_v[MROWS*DIM];
__device__ float g_o[MROWS*DIM];
__device__ float g_ff[MROWS*FFD];
__device__ float g_kp[BH*SEQ*MPAD];
__device__ float g_ctx[BH*MPAD*DH];
__device__ float g_ksum[BH*MPAD];
__device__ float g_kmax;

// ---------------- helpers ----------------
__device__ __forceinline__ void atomicMaxF(float* addr, float val) {
    int old = __float_as_int(*addr);
    while (__int_as_float(old) < val) {
        int assumed = old;
        old = atomicCAS((int*)addr, assumed, __float_as_int(val));
        if (old == assumed) break;
    }
}

__device__ __forceinline__ float gelu_tanh(float x) {
    float x3 = x * x * x;
    return 0.5f * x * (1.0f + tanhf(0.7978845608028654f * (x + 0.044715f * x3)));
}

__device__ __forceinline__ unsigned f2tf32(float x) {
    unsigned r;
    asm("cvt.rna.tf32.f32 %0, %1;" : "=r"(r) : "f"(x));
    return r;
}

__device__ __forceinline__ void mma_tf32(float (&d)[4], const unsigned (&a)[4], const unsigned (&b)[2]) {
    asm volatile(
        "mma.sync.aligned.m16n8k8.row.col.f32.tf32.tf32.f32 "
        "{%0,%1,%2,%3}, {%4,%5,%6,%7}, {%8,%9}, {%0,%1,%2,%3};\n"
        : "+f"(d[0]), "+f"(d[1]), "+f"(d[2]), "+f"(d[3])
        : "r"(a[0]), "r"(a[1]), "r"(a[2]), "r"(a[3]), "r"(b[0]), "r"(b[1]));
}

// ---------------- init / reset ----------------
__global__ void copy_src_kernel(const float* __restrict__ src) {
    int i = blockIdx.x * blockDim.x + threadIdx.x;
    if (i < MROWS*DIM) g_x[i] = src[i];
}

__global__ void reset_kernel() {
    int i = blockIdx.x * blockDim.x + threadIdx.x;
    if (i < BH*MPAD*DH) g_ctx[i] = 0.f;
    if (i < BH*MPAD)    g_ksum[i] = 0.f;
    if (i == 0)         g_kmax = __int_as_float(0xff800000);
}

// ---------------- LayerNorm ----------------
__global__ void __launch_bounds__(128) ln_kernel(
    const float* __restrict__ x, const float* __restrict__ g,
    const float* __restrict__ b, float* __restrict__ o)
{
    int row = blockIdx.x, tid = threadIdx.x, lane = tid & 31, w = tid >> 5;
    const float4 xv = ((const float4*)(x + (size_t)row*DIM))[tid];
    float s = xv.x + xv.y + xv.z + xv.w;
    float q = xv.x*xv.x + xv.y*xv.y + xv.z*xv.z + xv.w*xv.w;
    #pragma unroll
    for (int off = 16; off; off >>= 1) {
        s += __shfl_xor_sync(0xffffffffu, s, off);
        q += __shfl_xor_sync(0xffffffffu, q, off);
    }
    __shared__ float ss[4], sq[4];
    if (lane == 0) { ss[w] = s; sq[w] = q; }
    __syncthreads();
    float S = ss[0]+ss[1]+ss[2]+ss[3];
    float Q = sq[0]+sq[1]+sq[2]+sq[3];
    float mean = S * (1.0f/DIM);
    float var  = Q * (1.0f/DIM) - mean*mean;
    float inv  = rsqrtf(var + 1e-5f);
    float4 gv = ((const float4*)g)[tid];
    float4 bv = ((const float4*)b)[tid];
    float4 ov;
    ov.x = (xv.x - mean)*inv*gv.x + bv.x;
    ov.y = (xv.y - mean)*inv*gv.y + bv.y;
    ov.z = (xv.z - mean)*inv*gv.z + bv.z;
    ov.w = (xv.w - mean)*inv*gv.w + bv.w;
    ((float4*)(o + (size_t)row*DIM))[tid] = ov;
}

// ---------------- TF32 tensor-core GEMM ----------------
// C[M,N] = [res +] epilogue(A[M,K]*W[K,N] [+ bias]).  M%128==0, N%128==0, K%16==0.
// CTA tile 128x128x16, 256 threads = 8 warps (2x4), warp tile 64x32 via m16n8k8.
template<int BIASF, int RESF, int GELUF>
__global__ void __launch_bounds__(256) tgemm_kernel(
    const float* __restrict__ A, const float* __restrict__ W,
    const float* __restrict__ bias, const float* __restrict__ res,
    float* __restrict__ C, int M, int N, int K)
{
    __shared__ unsigned As[2][128][20];   // stride 20: conflict-free A frag loads
    __shared__ unsigned Bs[2][16][136];   // stride 136 (=8 mod 32): conflict-free B frag loads
    const int tid = threadIdx.x, lane = tid & 31, warp = tid >> 5;
    const int wm = warp >> 2, wn = warp & 3;
    const int bx = blockIdx.x, by = blockIdx.y;
    const float* Ab = A + (size_t)(by*128)*K;
    const float* Wb = W + bx*128;

    float acc[4][4][4];
    #pragma unroll
    for (int i = 0; i < 4; i++)
        #pragma unroll
        for (int j = 0; j < 4; j++)
            #pragma unroll
            for (int r = 0; r < 4; r++) acc[i][j][r] = 0.f;

    // A gmem mapping: f in [0,512): row=f>>2, col4=(f&3)*4  (two f per thread)
    const int ar0 = tid >> 2,            ac0 = (tid & 3) * 4;
    const int ar1 = (tid + 256) >> 2,    ac1 = ((tid + 256) & 3) * 4;
    // B gmem mapping: f in [0,512): row=f>>5, col4=(f&31)*4
    const int br0 = tid >> 5,            bc0 = (tid & 31) * 4;
    const int br1 = (tid + 256) >> 5,    bc1 = ((tid + 256) & 31) * 4;

    const int ntiles = K >> 4;

    // preload tile 0
    {
        float4 a0 = *(const float4*)(Ab + (size_t)ar0*K + ac0);
        float4 a1 = *(const float4*)(Ab + (size_t)ar1*K + ac1);
        float4 b0 = *(const float4*)(Wb + (size_t)br0*N + bc0);
        float4 b1 = *(const float4*)(Wb + (size_t)br1*N + bc1);
        As[0][ar0][ac0+0]=f2tf32(a0.x); As[0][ar0][ac0+1]=f2tf32(a0.y);
        As[0][ar0][ac0+2]=f2tf32(a0.z); As[0][ar0][ac0+3]=f2tf32(a0.w);
        As[0][ar1][ac1+0]=f2tf32(a1.x); As[0][ar1][ac1+1]=f2tf32(a1.y);
        As[0][ar1][ac1+2]=f2tf32(a1.z); As[0][ar1][ac1+3]=f2tf32(a1.w);
        Bs[0][br0][bc0+0]=f2tf32(b0.x); Bs[0][br0][bc0+1]=f2tf32(b0.y);
        Bs[0][br0][bc0+2]=f2tf32(b0.z); Bs[0][br0][bc0+3]=f2tf32(b0.w);
        Bs[0][br1][bc1+0]=f2tf32(b1.x); Bs[0][br1][bc1+1]=f2tf32(b1.y);
        Bs[0][br1][bc1+2]=f2tf32(b1.z); Bs[0][br1][bc1+3]=f2tf32(b1.w);
    }
    __syncthreads();

    const int arow_f = (lane >> 2);      // fragment row within 16
    const int acol_f = (lane & 3);       // fragment k within 4
    const int brow_f = (lane & 3);       // fragment k
    const int bcol_f = (lane >> 2);      // fragment n within 8

    #pragma unroll 1
    for (int kt = 0; kt < ntiles; kt++) {
        const int cur = kt & 1, nxt = cur ^ 1;
        const bool has = (kt + 1) < ntiles;
        float4 pa0, pa1, pb0, pb1;
        if (has) {
            const float* An = Ab + (kt+1)*16;
            const float* Bn = Wb + (size_t)((kt+1)*16)*N;
            pa0 = *(const float4*)(An + (size_t)ar0*K + ac0);
            pa1 = *(const float4*)(An + (size_t)ar1*K + ac1);
            pb0 = *(const float4*)(Bn + (size_t)br0*N + bc0);
            pb1 = *(const float4*)(Bn + (size_t)br1*N + bc1);
        }

        #pragma unroll
        for (int kk = 0; kk < 16; kk += 8) {
            unsigned af[4][4], bf[4][2];
            #pragma unroll
            for (int i = 0; i < 4; i++) {
                int mb = wm*64 + i*16 + arow_f;
                af[i][0] = As[cur][mb    ][kk + acol_f];
                af[i][1] = As[cur][mb + 8][kk + acol_f];
                af[i][2] = As[cur][mb    ][kk + acol_f + 4];
                af[i][3] = As[cur][mb + 8][kk + acol_f + 4];
            }
            #pragma unroll
            for (int j = 0; j < 4; j++) {
                int nb = wn*32 + j*8 + bcol_f;
                bf[j][0] = Bs[cur][kk + brow_f    ][nb];
                bf[j][1] = Bs[cur][kk + brow_f + 4][nb];
            }
            #pragma unroll
            for (int i = 0; i < 4; i++)
                #pragma unroll
                for (int j = 0; j < 4; j++)
                    mma_tf32(acc[i][j], af[i], bf[j]);
        }

        if (has) {
            As[nxt][ar0][ac0+0]=f2tf32(pa0.x); As[nxt][ar0][ac0+1]=f2tf32(pa0.y);
            As[nxt][ar0][ac0+2]=f2tf32(pa0.z); As[nxt][ar0][ac0+3]=f2tf32(pa0.w);
            As[nxt][ar1][ac1+0]=f2tf32(pa1.x); As[nxt][ar1][ac1+1]=f2tf32(pa1.y);
            As[nxt][ar1][ac1+2]=f2tf32(pa1.z); As[nxt][ar1][ac1+3]=f2tf32(pa1.w);
            Bs[nxt][br0][bc0+0]=f2tf32(pb0.x); Bs[nxt][br0][bc0+1]=f2tf32(pb0.y);
            Bs[nxt][br0][bc0+2]=f2tf32(pb0.z); Bs[nxt][br0][bc0+3]=f2tf32(pb0.w);
            Bs[nxt][br1][bc1+0]=f2tf32(pb1.x); Bs[nxt][br1][bc1+1]=f2tf32(pb1.y);
            Bs[nxt][br1][bc1+2]=f2tf32(pb1.z); Bs[nxt][br1][bc1+3]=f2tf32(pb1.w);
            __syncthreads();
        }
    }

    // epilogue
    const int row0 = by*128 + wm*64;
    const int col0 = bx*128 + wn*32;
    #pragma unroll
    for (int i = 0; i < 4; i++) {
        #pragma unroll
        for (int j = 0; j < 4; j++) {
            int r = row0 + i*16 + (lane >> 2);
            int c = col0 + j*8 + (lane & 3)*2;
            float b0 = 0.f, b1 = 0.f;
            if (BIASF) { b0 = bias[c]; b1 = bias[c+1]; }
            // rows r and r+8
            float v0 = acc[i][j][0] + b0;
            float v1 = acc[i][j][1] + b1;
            float v2 = acc[i][j][2] + b0;
            float v3 = acc[i][j][3] + b1;
            if (GELUF) { v0 = gelu_tanh(v0); v1 = gelu_tanh(v1); v2 = gelu_tanh(v2); v3 = gelu_tanh(v3); }
            if (RESF) {
                const float2 r0v = *(const float2*)(res + (size_t)r*N + c);
                const float2 r1v = *(const float2*)(res + (size_t)(r+8)*N + c);
                v0 += r0v.x; v1 += r0v.y; v2 += r1v.x; v3 += r1v.y;
            }
            *(float2*)(C + (size_t)r*N + c)     = make_float2(v0, v1);
            *(float2*)(C + (size_t)(r+8)*N + c) = make_float2(v2, v3);
        }
    }
}

// ---------------- Attention feature kernels (unchanged) ----------------
template<int MODE>
__global__ void __launch_bounds__(256) attn_kernel(const float* __restrict__ proj)
{
    extern __shared__ float sm[];
    float* projs = sm;
    float* qs    = projs + NB*PSTR;
    float* diag  = qs + 32*QSTR;
    float* ctxs  = diag + 32;
    float* ksums = ctxs + NB*DH;
    float* qps   = ksums + 272;

    const int tid = threadIdx.x, lane = tid & 31, w = tid >> 5;
    const int bh = blockIdx.y, b = bh >> 3, hh = bh & 7;
    const int n0 = blockIdx.x * 32;
    const float* inp = (MODE == 2) ? g_q : g_k;
    const float* src = inp + ((size_t)b*SEQ + n0)*DIM + hh*DH;

    for (int i = tid; i < NB*DH; i += 256)
        projs[(i>>6)*PSTR + (i&63)] = proj[i];
    for (int i = tid; i < 32*DH; i += 256)
        qs[(i>>6)*QSTR + (i&63)] = src[(size_t)(i>>6)*DIM + (i&63)] * DN;
    if (MODE == 2) {
        const float* cb = g_ctx + (size_t)bh*MPAD*DH;
        for (int i = tid; i < NB*DH; i += 256) ctxs[i] = cb[i];
        const float* kb = g_ksum + (size_t)bh*MPAD;
        for (int i = tid; i < NB; i += 256) ksums[i] = kb[i];
    }
    __syncthreads();
    if (MODE != 0 && tid < 32) {
        float s = 0.f;
        const float* qr = &qs[tid*QSTR];
        #pragma unroll 16
        for (int d = 0; d < DH; d++) s += qr[d]*qr[d];
        diag[tid] = 0.5f * s;
    }
    __syncthreads();

    const int r0 = w * 4;
    float acc[9][4];
    #pragma unroll
    for (int t = 0; t < 9; t++)
        #pragma unroll
        for (int r = 0; r < 4; r++) acc[t][r] = 0.f;

    for (int d0 = 0; d0 < DH; d0 += 8) {
        float qreg[4][8];
        #pragma unroll
        for (int r = 0; r < 4; r++)
            #pragma unroll
            for (int dd = 0; dd < 8; dd++)
                qreg[r][dd] = qs[(r0+r)*QSTR + d0 + dd];
        #pragma unroll
        for (int t = 0; t < 9; t++) {
            int j = lane + 32*t;
            if (j < NB) {
                const float* pr = &projs[j*PSTR + d0];
                #pragma unroll
                for (int dd = 0; dd < 8; dd++) {
                    float p = pr[dd];
                    acc[t][0] += qreg[0][dd]*p;
                    acc[t][1] += qreg[1][dd]*p;
                    acc[t][2] += qreg[2][dd]*p;
                    acc[t][3] += qreg[3][dd]*p;
                }
            }
        }
    }

    if (MODE == 0) {
        float m = __int_as_float(0xff800000);
        #pragma unroll
        for (int t = 0; t < 9; t++) {
            int j = lane + 32*t;
            if (j < NB) {
                #pragma unroll
                for (int r = 0; r < 4; r++) m = fmaxf(m, acc[t][r]);
            }
        }
        #pragma unroll
        for (int off = 16; off; off >>= 1) m = fmaxf(m, __shfl_xor_sync(0xffffffffu, m, off));
        __shared__ float wm[8];
        if (lane == 0) wm[w] = m;
        __syncthreads();
        if (tid == 0) {
            float mm = wm[0];
            #pragma unroll
            for (int i = 1; i < 8; i++) mm = fmaxf(mm, wm[i]);
            atomicMaxF(&g_kmax, mm);
        }
        return;
    }

    if (MODE == 1) {
        float km = g_kmax;
        #pragma unroll
        for (int r = 0; r < 4; r++) {
            int rr = r0 + r;
            float dg = diag[rr];
            float* orow = g_kp + ((size_t)bh*SEQ + n0 + rr)*MPAD;
            #pragma unroll
            for (int t = 0; t < 9; t++) {
                int j = lane + 32*t;
                if (j < NB) orow[j] = RATIO * (expf(acc[t][r] - dg - km) + EPSF);
            }
            for (int mz = NB + lane; mz < MPAD; mz += 32) orow[mz] = 0.f;
        }
        return;
    }

    #pragma unroll
    for (int r = 0; r < 4; r++) {
        int rr = r0 + r;
        float m = __int_as_float(0xff800000);
        #pragma unroll
        for (int t = 0; t < 9; t++) {
            int j = lane + 32*t;
            if (j < NB) m = fmaxf(m, acc[t][r]);
        }
        #pragma unroll
        for (int off = 16; off; off >>= 1) m = fmaxf(m, __shfl_xor_sync(0xffffffffu, m, off));
        float dg = diag[rr];
        float* qrow = &qps[rr*QPSTR];
        #pragma unroll
        for (int t = 0; t < 9; t++) {
            int j = lane + 32*t;
            if (j < NB) qrow[j] = RATIO * (expf(acc[t][r] - dg - m) + EPSF);
        }
    }
    __syncwarp();

    float ov[4][2];
    #pragma unroll
    for (int r = 0; r < 4; r++) { ov[r][0] = 0.f; ov[r][1] = 0.f; }
    #pragma unroll 2
    for (int m = 0; m < NB; m++) {
        float2 c = *(const float2*)&ctxs[m*DH + 2*lane];
        #pragma unroll
        for (int r = 0; r < 4; r++) {
            float p = qps[(r0+r)*QPSTR + m];
            ov[r][0] += p * c.x;
            ov[r][1] += p * c.y;
        }
    }
    float dnm[4] = {0.f, 0.f, 0.f, 0.f};
    for (int m = lane; m < NB; m += 32) {
        float s = ksums[m];
        dnm[0] += qps[(r0+0)*QPSTR + m]*s;
        dnm[1] += qps[(r0+1)*QPSTR + m]*s;
        dnm[2] += qps[(r0+2)*QPSTR + m]*s;
        dnm[3] += qps[(r0+3)*QPSTR + m]*s;
    }
    #pragma unroll
    for (int off = 16; off; off >>= 1) {
        dnm[0] += __shfl_xor_sync(0xffffffffu, dnm[0], off);
        dnm[1] += __shfl_xor_sync(0xffffffffu, dnm[1], off);
        dnm[2] += __shfl_xor_sync(0xffffffffu, dnm[2], off);
        dnm[3] += __shfl_xor_sync(0xffffffffu, dnm[3], off);
    }
    #pragma unroll
    for (int r = 0; r < 4; r++) {
        int rr = r0 + r;
        float inv = 1.0f / dnm[r];
        float* orow = g_o + ((size_t)b*SEQ + n0 + rr)*DIM + hh*DH;
        float2 res2;
        res2.x = ov[r][0] * inv;
        res2.y = ov[r][1] * inv;
        *(float2*)&orow[2*lane] = res2;
    }
}

// ---------------- ctx kernel (unchanged) ----------------
__global__ void __launch_bounds__(256) ctx_kernel()
{
    __shared__ float As[16][64];
    __shared__ float Bs[16][64];
    int tid = threadIdx.x;
    int m0 = blockIdx.x * 64;
    int bh = blockIdx.y, b = bh >> 3, hh = bh & 7;
    int nbase = blockIdx.z * (SEQ / SPLITK);
    int lrow = tid >> 4, lcol = (tid & 15) * 4;
    int tx = tid & 15, ty = tid >> 4;
    float acc[4][4];
    #pragma unroll
    for (int i = 0; i < 4; i++)
        #pragma unroll
        for (int j = 0; j < 4; j++) acc[i][j] = 0.f;
    float ks[4] = {0.f, 0.f, 0.f, 0.f};
    const float* kpb = g_kp + (size_t)bh*SEQ*MPAD + m0;
    const float* vb  = g_v + (size_t)b*SEQ*DIM + hh*DH;
    for (int k0 = 0; k0 < SEQ/SPLITK; k0 += 16) {
        int n = nbase + k0;
        *(float4*)&As[lrow][lcol] = *(const float4*)(kpb + (size_t)(n+lrow)*MPAD + lcol);
        *(float4*)&Bs[lrow][lcol] = *(const float4*)(vb  + (size_t)(n+lrow)*DIM  + lcol);
        __syncthreads();
        #pragma unroll
        for (int kk = 0; kk < 16; kk++) {
            float4 a = *(float4*)&As[kk][ty*4];
            float4 bv = *(float4*)&Bs[kk][tx*4];
            float av_[4] = {a.x, a.y, a.z, a.w};
            float bv_[4] = {bv.x, bv.y, bv.z, bv.w};
            #pragma unroll
            for (int i = 0; i < 4; i++)
                #pragma unroll
                for (int j = 0; j < 4; j++)
                    acc[i][j] += av_[i]*bv_[j];
            if (tx == 0) { ks[0]+=a.x; ks[1]+=a.y; ks[2]+=a.z; ks[3]+=a.w; }
        }
        __syncthreads();
    }
    float* cb = g_ctx + (size_t)bh*MPAD*DH;
    #pragma unroll
    for (int i = 0; i < 4; i++)
        #pragma unroll
        for (int j = 0; j < 4; j++)
            atomicAdd(&cb[(m0 + ty*4 + i)*DH + tx*4 + j], acc[i][j]);
    if (tx == 0) {
        #pragma unroll
        for (int i = 0; i < 4; i++)
            atomicAdd(&g_ksum[bh*MPAD + m0 + ty*4 + i], ks[i]);
    }
}

// ---------------- final fc ----------------
__global__ void __launch_bounds__(256) fc_kernel(
    const float* __restrict__ x, const float* __restrict__ w,
    const float* __restrict__ bias, float* __restrict__ out)
{
    __shared__ float xs[8*DIM];
    int tid = threadIdx.x;
    int m0 = blockIdx.x * 8;
    for (int i = tid; i < 8*DIM/4; i += 256)
        ((float4*)xs)[i] = ((const float4*)(x + (size_t)m0*DIM))[i];
    __syncthreads();
    int r = tid >> 5, c = tid & 31;
    float acc = 0.f;
    const float* xr = &xs[r*DIM];
    #pragma unroll 8
    for (int k = 0; k < DIM; k++) acc += xr[k] * w[k*OUTD + c];
    out[(size_t)(m0 + r)*OUTD + c] = acc + bias[c];
}

// ---------------- host launcher ----------------
extern "C" void kernel_launch(void* const* d_in, const int* in_sizes, int n_in,
                              void* d_out, int out_size)
{
    (void)in_sizes; (void)n_in; (void)out_size;
    const float* src  = (const float*)d_in[0];
    const float* proj = (const float*)d_in[1];
    const float* ln1g = (const float*)d_in[2];
    const float* ln1b = (const float*)d_in[3];
    const float* Wq   = (const float*)d_in[4];
    const float* Wk   = (const float*)d_in[5];
    const float* Wv   = (const float*)d_in[6];
    const float* Wo   = (const float*)d_in[7];
    const float* bo   = (const float*)d_in[8];
    const float* ln2g = (const float*)d_in[9];
    const float* ln2b = (const float*)d_in[10];
    const float* W1   = (const float*)d_in[11];
    const float* b1   = (const float*)d_in[12];
    const float* W2   = (const float*)d_in[13];
    const float* b2   = (const float*)d_in[14];
    const float* fcw  = (const float*)d_in[15];
    const float* fcb  = (const float*)d_in[16];
    float* out = (float*)d_out;

    float *xp, *hp, *qb, *kb, *vb, *ob, *ffb;
    cudaGetSymbolAddress((void**)&xp,  g_x);
    cudaGetSymbolAddress((void**)&hp,  g_h);
    cudaGetSymbolAddress((void**)&qb,  g_q);
    cudaGetSymbolAddress((void**)&kb,  g_k);
    cudaGetSymbolAddress((void**)&vb,  g_v);
    cudaGetSymbolAddress((void**)&ob,  g_o);
    cudaGetSymbolAddress((void**)&ffb, g_ff);

    const int smem01 = (NB*PSTR + 32*QSTR + 32) * 4;
    const int smem2  = (NB*PSTR + 32*QSTR + 32 + NB*DH + 272 + 32*QPSTR) * 4;
    cudaFuncSetAttribute(attn_kernel<0>, cudaFuncAttributeMaxDynamicSharedMemorySize, smem01);
    cudaFuncSetAttribute(attn_kernel<1>, cudaFuncAttributeMaxDynamicSharedMemorySize, smem01);
    cudaFuncSetAttribute(attn_kernel<2>, cudaFuncAttributeMaxDynamicSharedMemorySize, smem2);

    copy_src_kernel<<<(MROWS*DIM + 255)/256, 256>>>(src);

    dim3 gg(DIM/128, MROWS/128);       // 4 x 256
    dim3 gf(FFD/128, MROWS/128);       // 16 x 256
    dim3 ag(SEQ/32, BH);               // 256 x 32

    for (int L = 0; L < DEPTH; L++) {
        const float* pj = proj + (size_t)L*NB*DH;
        ln_kernel<<<MROWS, 128>>>(xp, ln1g + L*DIM, ln1b + L*DIM, hp);
        tgemm_kernel<0,0,0><<<gg, 256>>>(hp, Wq + (size_t)L*DIM*DIM, 0, 0, qb, MROWS, DIM, DIM);
        tgemm_kernel<0,0,0><<<gg, 256>>>(hp, Wk + (size_t)L*DIM*DIM, 0, 0, kb, MROWS, DIM, DIM);
        tgemm_kernel<0,0,0><<<gg, 256>>>(hp, Wv + (size_t)L*DIM*DIM, 0, 0, vb, MROWS, DIM, DIM);
        reset_kernel<<<(BH*MPAD*DH + 255)/256, 256>>>();
        attn_kernel<0><<<ag, 256, smem01>>>(pj);
        attn_kernel<1><<<ag, 256, smem01>>>(pj);
        ctx_kernel<<<dim3(MPAD/64, BH, SPLITK), 256>>>();
        attn_kernel<2><<<ag, 256, smem2>>>(pj);
        tgemm_kernel<1,1,0><<<gg, 256>>>(ob, Wo + (size_t)L*DIM*DIM, bo + L*DIM, xp, xp, MROWS, DIM, DIM);
        ln_kernel<<<MROWS, 128>>>(xp, ln2g + L*DIM, ln2b + L*DIM, hp);
        tgemm_kernel<1,0,1><<<gf, 256>>>(hp, W1 + (size_t)L*DIM*FFD, b1 + L*FFD, 0, ffb, MROWS, FFD, DIM);
        tgemm_kernel<1,1,0><<<gg, 256>>>(ffb, W2 + (size_t)L*FFD*DIM, b2 + L*DIM, xp, xp, MROWS, DIM, FFD);
    }
    fc_kernel<<<MROWS/8, 256>>>(xp, fcw, fcb, out);
}

// round 3
// speedup vs baseline: 2.8040x; 1.5782x over previous
#include <cuda_runtime.h>
#include <math.h>

#define DEPTH  6
#define DIM    512
#define HEADS  8
#define DH     64
#define NB     266
#define FFD    2048
#define OUTD   32
#define BATCH  4
#define SEQ    8192
#define MROWS  (BATCH*SEQ)   // 32768
#define BH     (BATCH*HEADS) // 32
#define MPAD   320
#define CTXW   80            // ctx row width (64 v + 1 ones + pad)
#define ASTR   68            // A-tile smem stride
#define BSTR   332           // B/qp smem stride
#define CSTR   88            // ctx smem stride
#define EPSF   1e-4f
#define DN     0.3535533905932738f
#define RATIO  0.06131393394849658f
#define SPLITK 4

// ---------------- scratch ----------------
__device__ float g_x[MROWS*DIM];
__device__ float g_h[MROWS*DIM];
__device__ float g_q[MROWS*DIM];
__device__ float g_k[MROWS*DIM];
__device__ float g_v[MROWS*DIM];
__device__ float g_o[MROWS*DIM];
__device__ float g_ff[MROWS*FFD];
__device__ float g_kp[(size_t)BH*SEQ*MPAD];
__device__ float g_ctx[BH*MPAD*CTXW];
__device__ float g_diag[BH*SEQ];
__device__ unsigned g_projT[DH*MPAD];
__device__ float g_kmax;

// ---------------- helpers ----------------
__device__ __forceinline__ void atomicMaxF(float* addr, float val) {
    int old = __float_as_int(*addr);
    while (__int_as_float(old) < val) {
        int assumed = old;
        old = atomicCAS((int*)addr, assumed, __float_as_int(val));
        if (old == assumed) break;
    }
}

// fast exp: pure FMA pipe (avoids MUFU.EX2 throughput wall)
__device__ __forceinline__ float fast_exp(float x) {
    float t = x * 1.4426950408889634f;
    t = fminf(fmaxf(t, -126.0f), 126.0f);
    float z = t + 12582912.0f;
    int n = __float_as_int(z) - 0x4B400000;
    float f = t - (z - 12582912.0f);
    float p = 1.33335581e-3f;
    p = fmaf(p, f, 9.61812911e-3f);
    p = fmaf(p, f, 5.55041087e-2f);
    p = fmaf(p, f, 2.40226507e-1f);
    p = fmaf(p, f, 6.93147181e-1f);
    p = fmaf(p, f, 1.0f);
    return p * __int_as_float((n + 127) << 23);
}

// fast reciprocal (valid for x in ~[1e-30,1e30]); FMA only
__device__ __forceinline__ float fast_rcp(float x) {
    float y = __int_as_float(0x7EF311C3 - __float_as_int(x));
    y = y * (2.0f - x * y);
    y = y * (2.0f - x * y);
    y = y * (2.0f - x * y);
    return y;
}

__device__ __forceinline__ float gelu_fast(float x) {
    float u = 0.7978845608028654f * (x + 0.044715f * x * x * x);
    u = fminf(fmaxf(u, -9.0f), 9.0f);
    float E = fast_exp(2.0f * u);
    float th = 1.0f - 2.0f * fast_rcp(E + 1.0f);
    return 0.5f * x * (1.0f + th);
}

__device__ __forceinline__ unsigned f2tf32(float x) {
    unsigned r;
    asm("cvt.rna.tf32.f32 %0, %1;" : "=r"(r) : "f"(x));
    return r;
}

__device__ __forceinline__ void mma_tf32(float (&d)[4], const unsigned (&a)[4], const unsigned (&b)[2]) {
    asm volatile(
        "mma.sync.aligned.m16n8k8.row.col.f32.tf32.tf32.f32 "
        "{%0,%1,%2,%3}, {%4,%5,%6,%7}, {%8,%9}, {%0,%1,%2,%3};\n"
        : "+f"(d[0]), "+f"(d[1]), "+f"(d[2]), "+f"(d[3])
        : "r"(a[0]), "r"(a[1]), "r"(a[2]), "r"(a[3]), "r"(b[0]), "r"(b[1]));
}

// ---------------- init / reset ----------------
__global__ void copy_src_kernel(const float* __restrict__ src) {
    int i = blockIdx.x * blockDim.x + threadIdx.x;
    if (i < MROWS*DIM) g_x[i] = src[i];
}

__global__ void reset_kernel() {
    int i = blockIdx.x * blockDim.x + threadIdx.x;
    if (i < BH*MPAD*CTXW) g_ctx[i] = 0.f;
    if (i == 0) g_kmax = __int_as_float(0xff800000);
}

__global__ void projt_kernel(const float* __restrict__ proj) {
    int i = blockIdx.x * blockDim.x + threadIdx.x;
    if (i < DH*MPAD) {
        int d = i / MPAD, f = i % MPAD;
        float v = (f < NB) ? proj[f*DH + d] : 0.f;
        g_projT[i] = f2tf32(v);
    }
}

// ---------------- LayerNorm ----------------
__global__ void __launch_bounds__(128) ln_kernel(
    const float* __restrict__ x, const float* __restrict__ g,
    const float* __restrict__ b, float* __restrict__ o)
{
    int row = blockIdx.x, tid = threadIdx.x, lane = tid & 31, w = tid >> 5;
    const float4 xv = ((const float4*)(x + (size_t)row*DIM))[tid];
    float s = xv.x + xv.y + xv.z + xv.w;
    float q = xv.x*xv.x + xv.y*xv.y + xv.z*xv.z + xv.w*xv.w;
    #pragma unroll
    for (int off = 16; off; off >>= 1) {
        s += __shfl_xor_sync(0xffffffffu, s, off);
        q += __shfl_xor_sync(0xffffffffu, q, off);
    }
    __shared__ float ss[4], sq[4];
    if (lane == 0) { ss[w] = s; sq[w] = q; }
    __syncthreads();
    float S = ss[0]+ss[1]+ss[2]+ss[3];
    float Q = sq[0]+sq[1]+sq[2]+sq[3];
    float mean = S * (1.0f/DIM);
    float var  = Q * (1.0f/DIM) - mean*mean;
    float inv  = rsqrtf(var + 1e-5f);
    float4 gv = ((const float4*)g)[tid];
    float4 bv = ((const float4*)b)[tid];
    float4 ov;
    ov.x = (xv.x - mean)*inv*gv.x + bv.x;
    ov.y = (xv.y - mean)*inv*gv.y + bv.y;
    ov.z = (xv.z - mean)*inv*gv.z + bv.z;
    ov.w = (xv.w - mean)*inv*gv.w + bv.w;
    ((float4*)(o + (size_t)row*DIM))[tid] = ov;
}

// ---------------- TF32 tensor-core GEMM (dense layers) ----------------
template<int BIASF, int RESF, int GELUF>
__global__ void __launch_bounds__(256) tgemm_kernel(
    const float* __restrict__ A, const float* __restrict__ W,
    const float* __restrict__ bias, const float* __restrict__ res,
    float* __restrict__ C, int M, int N, int K)
{
    __shared__ unsigned As[2][128][20];
    __shared__ unsigned Bs[2][16][136];
    const int tid = threadIdx.x, lane = tid & 31, warp = tid >> 5;
    const int wm = warp >> 2, wn = warp & 3;
    const int bx = blockIdx.x, by = blockIdx.y;
    const float* Ab = A + (size_t)(by*128)*K;
    const float* Wb = W + bx*128;

    float acc[4][4][4];
    #pragma unroll
    for (int i = 0; i < 4; i++)
        #pragma unroll
        for (int j = 0; j < 4; j++)
            #pragma unroll
            for (int r = 0; r < 4; r++) acc[i][j][r] = 0.f;

    const int ar0 = tid >> 2,            ac0 = (tid & 3) * 4;
    const int ar1 = (tid + 256) >> 2,    ac1 = ((tid + 256) & 3) * 4;
    const int br0 = tid >> 5,            bc0 = (tid & 31) * 4;
    const int br1 = (tid + 256) >> 5,    bc1 = ((tid + 256) & 31) * 4;

    const int ntiles = K >> 4;
    {
        float4 a0 = *(const float4*)(Ab + (size_t)ar0*K + ac0);
        float4 a1 = *(const float4*)(Ab + (size_t)ar1*K + ac1);
        float4 b0 = *(const float4*)(Wb + (size_t)br0*N + bc0);
        float4 b1 = *(const float4*)(Wb + (size_t)br1*N + bc1);
        As[0][ar0][ac0+0]=f2tf32(a0.x); As[0][ar0][ac0+1]=f2tf32(a0.y);
        As[0][ar0][ac0+2]=f2tf32(a0.z); As[0][ar0][ac0+3]=f2tf32(a0.w);
        As[0][ar1][ac1+0]=f2tf32(a1.x); As[0][ar1][ac1+1]=f2tf32(a1.y);
        As[0][ar1][ac1+2]=f2tf32(a1.z); As[0][ar1][ac1+3]=f2tf32(a1.w);
        Bs[0][br0][bc0+0]=f2tf32(b0.x); Bs[0][br0][bc0+1]=f2tf32(b0.y);
        Bs[0][br0][bc0+2]=f2tf32(b0.z); Bs[0][br0][bc0+3]=f2tf32(b0.w);
        Bs[0][br1][bc1+0]=f2tf32(b1.x); Bs[0][br1][bc1+1]=f2tf32(b1.y);
        Bs[0][br1][bc1+2]=f2tf32(b1.z); Bs[0][br1][bc1+3]=f2tf32(b1.w);
    }
    __syncthreads();

    const int qg = lane >> 2, qt = lane & 3;

    #pragma unroll 1
    for (int kt = 0; kt < ntiles; kt++) {
        const int cur = kt & 1, nxt = cur ^ 1;
        const bool has = (kt + 1) < ntiles;
        float4 pa0, pa1, pb0, pb1;
        if (has) {
            const float* An = Ab + (kt+1)*16;
            const float* Bn = Wb + (size_t)((kt+1)*16)*N;
            pa0 = *(const float4*)(An + (size_t)ar0*K + ac0);
            pa1 = *(const float4*)(An + (size_t)ar1*K + ac1);
            pb0 = *(const float4*)(Bn + (size_t)br0*N + bc0);
            pb1 = *(const float4*)(Bn + (size_t)br1*N + bc1);
        }
        #pragma unroll
        for (int kk = 0; kk < 16; kk += 8) {
            unsigned af[4][4], bf[4][2];
            #pragma unroll
            for (int i = 0; i < 4; i++) {
                int mb = wm*64 + i*16 + qg;
                af[i][0] = As[cur][mb    ][kk + qt];
                af[i][1] = As[cur][mb + 8][kk + qt];
                af[i][2] = As[cur][mb    ][kk + qt + 4];
                af[i][3] = As[cur][mb + 8][kk + qt + 4];
            }
            #pragma unroll
            for (int j = 0; j < 4; j++) {
                int nb = wn*32 + j*8 + qg;
                bf[j][0] = Bs[cur][kk + qt    ][nb];
                bf[j][1] = Bs[cur][kk + qt + 4][nb];
            }
            #pragma unroll
            for (int i = 0; i < 4; i++)
                #pragma unroll
                for (int j = 0; j < 4; j++)
                    mma_tf32(acc[i][j], af[i], bf[j]);
        }
        if (has) {
            As[nxt][ar0][ac0+0]=f2tf32(pa0.x); As[nxt][ar0][ac0+1]=f2tf32(pa0.y);
            As[nxt][ar0][ac0+2]=f2tf32(pa0.z); As[nxt][ar0][ac0+3]=f2tf32(pa0.w);
            As[nxt][ar1][ac1+0]=f2tf32(pa1.x); As[nxt][ar1][ac1+1]=f2tf32(pa1.y);
            As[nxt][ar1][ac1+2]=f2tf32(pa1.z); As[nxt][ar1][ac1+3]=f2tf32(pa1.w);
            Bs[nxt][br0][bc0+0]=f2tf32(pb0.x); Bs[nxt][br0][bc0+1]=f2tf32(pb0.y);
            Bs[nxt][br0][bc0+2]=f2tf32(pb0.z); Bs[nxt][br0][bc0+3]=f2tf32(pb0.w);
            Bs[nxt][br1][bc1+0]=f2tf32(pb1.x); Bs[nxt][br1][bc1+1]=f2tf32(pb1.y);
            Bs[nxt][br1][bc1+2]=f2tf32(pb1.z); Bs[nxt][br1][bc1+3]=f2tf32(pb1.w);
            __syncthreads();
        }
    }

    const int row0 = by*128 + wm*64;
    const int col0 = bx*128 + wn*32;
    #pragma unroll
    for (int i = 0; i < 4; i++) {
        #pragma unroll
        for (int j = 0; j < 4; j++) {
            int r = row0 + i*16 + qg;
            int c = col0 + j*8 + qt*2;
            float b0 = 0.f, b1 = 0.f;
            if (BIASF) { b0 = bias[c]; b1 = bias[c+1]; }
            float v0 = acc[i][j][0] + b0;
            float v1 = acc[i][j][1] + b1;
            float v2 = acc[i][j][2] + b0;
            float v3 = acc[i][j][3] + b1;
            if (GELUF) { v0 = gelu_fast(v0); v1 = gelu_fast(v1); v2 = gelu_fast(v2); v3 = gelu_fast(v3); }
            if (RESF) {
                const float2 r0v = *(const float2*)(res + (size_t)r*N + c);
                const float2 r1v = *(const float2*)(res + (size_t)(r+8)*N + c);
                v0 += r0v.x; v1 += r0v.y; v2 += r1v.x; v3 += r1v.y;
            }
            *(float2*)(C + (size_t)r*N + c)     = make_float2(v0, v1);
            *(float2*)(C + (size_t)(r+8)*N + c) = make_float2(v2, v3);
        }
    }
}

// ---------------- feature-map kernels (TF32 MMA) ----------------
// ISQ=0: k path — write raw xp (padded) to g_kp, diag to g_diag, blockmax -> g_kmax
// ISQ=1: q path — xq MMA + rowmax + exp -> qp(smem) -> MMA with ctxExt -> g_o
template<int ISQ>
__global__ void __launch_bounds__(256) xfeat_kernel()
{
    extern __shared__ unsigned smu[];
    unsigned* As = smu;                          // 64*ASTR
    unsigned* Bs = As + 64*ASTR;                 // 64*BSTR
    unsigned* Cs = Bs + 64*BSTR;                 // 320*CSTR (ISQ only)
    float* s_aux = (float*)(ISQ ? (Cs + MPAD*CSTR) : Cs);
    float* s_diag = s_aux;                       // 64
    float* s_rmax = s_diag + 64;                 // 64*4
    float* s_dnm  = s_rmax + 256;                // 64
    float* s_wm   = s_dnm + 64;                  // 8

    const int tid = threadIdx.x, lane = tid & 31, warp = tid >> 5;
    const int qg = lane >> 2, qt = lane & 3;
    const int wm = warp >> 2, wn = warp & 3;
    const int bh = blockIdx.y, b = bh >> 3, hh = bh & 7;
    const int n0 = blockIdx.x * 64;
    const float* src = (ISQ ? g_q : g_k) + ((size_t)b*SEQ + n0)*DIM + hh*DH;

    // loads
    #pragma unroll
    for (int i = tid; i < 64*16; i += 256) {
        int r = i >> 4, c4 = (i & 15) * 4;
        float4 v = *(const float4*)(src + (size_t)r*DIM + c4);
        As[r*ASTR + c4+0] = f2tf32(v.x*DN);
        As[r*ASTR + c4+1] = f2tf32(v.y*DN);
        As[r*ASTR + c4+2] = f2tf32(v.z*DN);
        As[r*ASTR + c4+3] = f2tf32(v.w*DN);
    }
    #pragma unroll
    for (int i = tid; i < 64*80; i += 256) {
        int r = i / 80, c4 = (i % 80) * 4;
        uint4 v = *(const uint4*)(g_projT + r*MPAD + c4);
        Bs[r*BSTR + c4+0] = v.x;
        Bs[r*BSTR + c4+1] = v.y;
        Bs[r*BSTR + c4+2] = v.z;
        Bs[r*BSTR + c4+3] = v.w;
    }
    if (ISQ) {
        const float* cb = g_ctx + (size_t)bh*MPAD*CTXW;
        #pragma unroll
        for (int i = tid; i < MPAD*20; i += 256) {
            int r = i / 20, c4 = (i % 20) * 4;
            float4 v = *(const float4*)(cb + r*CTXW + c4);
            Cs[r*CSTR + c4+0] = f2tf32(v.x);
            Cs[r*CSTR + c4+1] = f2tf32(v.y);
            Cs[r*CSTR + c4+2] = f2tf32(v.z);
            Cs[r*CSTR + c4+3] = f2tf32(v.w);
        }
    }
    __syncthreads();

    // diag
    if (tid < 64) {
        float s = 0.f;
        #pragma unroll 16
        for (int d = 0; d < DH; d++) {
            float v = __uint_as_float(As[tid*ASTR + d]);
            s += v*v;
        }
        s = 0.5f * s;
        s_diag[tid] = s;
        if (!ISQ) g_diag[(size_t)bh*SEQ + n0 + tid] = s;
    }

    // GEMM1: xp[64,320] = A[64,64] @ projT[64,320]
    float acc1[2][10][4];
    #pragma unroll
    for (int i = 0; i < 2; i++)
        #pragma unroll
        for (int j = 0; j < 10; j++)
            #pragma unroll
            for (int r = 0; r < 4; r++) acc1[i][j][r] = 0.f;

    #pragma unroll
    for (int kk = 0; kk < 64; kk += 8) {
        unsigned af[2][4], bf[10][2];
        #pragma unroll
        for (int i = 0; i < 2; i++) {
            const unsigned* ap = As + (wm*32 + i*16 + qg)*ASTR + kk + qt;
            af[i][0] = ap[0];
            af[i][1] = ap[8*ASTR];
            af[i][2] = ap[4];
            af[i][3] = ap[8*ASTR + 4];
        }
        #pragma unroll
        for (int j = 0; j < 10; j++) {
            const unsigned* bp = Bs + (kk + qt)*BSTR + wn*80 + j*8 + qg;
            bf[j][0] = bp[0];
            bf[j][1] = bp[4*BSTR];
        }
        #pragma unroll
        for (int i = 0; i < 2; i++)
            #pragma unroll
            for (int j = 0; j < 10; j++)
                mma_tf32(acc1[i][j], af[i], bf[j]);
    }

    float* fBs = (float*)Bs;

    if (!ISQ) {
        // block max (masked) -> atomicMax
        float m = __int_as_float(0xff800000);
        #pragma unroll
        for (int i = 0; i < 2; i++)
            #pragma unroll
            for (int j = 0; j < 10; j++)
                #pragma unroll
                for (int r = 0; r < 4; r++) {
                    int col = wn*80 + j*8 + qt*2 + (r & 1);
                    if (col < NB) m = fmaxf(m, acc1[i][j][r]);
                }
        #pragma unroll
        for (int off = 16; off; off >>= 1) m = fmaxf(m, __shfl_xor_sync(0xffffffffu, m, off));
        if (lane == 0) s_wm[warp] = m;
        __syncthreads();
        if (tid == 0) {
            float mm = s_wm[0];
            #pragma unroll
            for (int i = 1; i < 8; i++) mm = fmaxf(mm, s_wm[i]);
            atomicMaxF(&g_kmax, mm);
        }
        // stage raw xp into Bs (fp32), masked cols -> 0
        #pragma unroll
        for (int i = 0; i < 2; i++)
            #pragma unroll
            for (int j = 0; j < 10; j++)
                #pragma unroll
                for (int r = 0; r < 4; r++) {
                    int row = wm*32 + i*16 + qg + 8*(r >> 1);
                    int col = wn*80 + j*8 + qt*2 + (r & 1);
                    fBs[row*BSTR + col] = (col < NB) ? acc1[i][j][r] : 0.f;
                }
        __syncthreads();
        // coalesced copy to g_kp
        #pragma unroll
        for (int i = tid; i < 64*80; i += 256) {
            int r = i / 80, c4 = (i % 80) * 4;
            float4 v;
            v.x = fBs[r*BSTR + c4+0];
            v.y = fBs[r*BSTR + c4+1];
            v.z = fBs[r*BSTR + c4+2];
            v.w = fBs[r*BSTR + c4+3];
            *(float4*)(g_kp + ((size_t)bh*SEQ + n0 + r)*MPAD + c4) = v;
        }
        return;
    }

    // ===== ISQ: rowmax =====
    #pragma unroll
    for (int i = 0; i < 2; i++) {
        #pragma unroll
        for (int h = 0; h < 2; h++) {
            float m = __int_as_float(0xff800000);
            #pragma unroll
            for (int j = 0; j < 10; j++) {
                #pragma unroll
                for (int rb = 0; rb < 2; rb++) {
                    int r = 2*h + rb;
                    int col = wn*80 + j*8 + qt*2 + rb;
                    if (col < NB) m = fmaxf(m, acc1[i][j][r]);
                }
            }
            m = fmaxf(m, __shfl_xor_sync(0xffffffffu, m, 1));
            m = fmaxf(m, __shfl_xor_sync(0xffffffffu, m, 2));
            if (qt == 0) s_rmax[(wm*32 + i*16 + qg + 8*h)*4 + wn] = m;
        }
    }
    __syncthreads();

    // exp -> qp (tf32) into Bs
    float sub[2][2];
    #pragma unroll
    for (int i = 0; i < 2; i++)
        #pragma unroll
        for (int h = 0; h < 2; h++) {
            int row = wm*32 + i*16 + qg + 8*h;
            float m = fmaxf(fmaxf(s_rmax[row*4+0], s_rmax[row*4+1]),
                            fmaxf(s_rmax[row*4+2], s_rmax[row*4+3]));
            sub[i][h] = m + s_diag[row];
        }
    #pragma unroll
    for (int i = 0; i < 2; i++)
        #pragma unroll
        for (int j = 0; j < 10; j++)
            #pragma unroll
            for (int r = 0; r < 4; r++) {
                int row = wm*32 + i*16 + qg + 8*(r >> 1);
                int col = wn*80 + j*8 + qt*2 + (r & 1);
                float v = 0.f;
                if (col < NB) v = RATIO * (fast_exp(acc1[i][j][r] - sub[i][r >> 1]) + EPSF);
                Bs[row*BSTR + col] = f2tf32(v);
            }
    __syncthreads();

    // GEMM2: o[64,80] = qp[64,320] @ ctxExt[320,80]
    const int wm2 = warp >> 1, wn2 = warp & 1;
    float acc2[5][4];
    #pragma unroll
    for (int j = 0; j < 5; j++)
        #pragma unroll
        for (int r = 0; r < 4; r++) acc2[j][r] = 0.f;

    #pragma unroll 4
    for (int kk = 0; kk < MPAD; kk += 8) {
        unsigned af[4], bf[5][2];
        const unsigned* ap = Bs + (wm2*16 + qg)*BSTR + kk + qt;
        af[0] = ap[0];
        af[1] = ap[8*BSTR];
        af[2] = ap[4];
        af[3] = ap[8*BSTR + 4];
        #pragma unroll
        for (int j = 0; j < 5; j++) {
            const unsigned* bp = Cs + (kk + qt)*CSTR + wn2*40 + j*8 + qg;
            bf[j][0] = bp[0];
            bf[j][1] = bp[4*CSTR];
        }
        #pragma unroll
        for (int j = 0; j < 5; j++)
            mma_tf32(acc2[j], af, bf[j]);
    }

    // denominator broadcast (col 64)
    #pragma unroll
    for (int j = 0; j < 5; j++)
        #pragma unroll
        for (int r = 0; r < 4; r++) {
            int col = wn2*40 + j*8 + qt*2 + (r & 1);
            if (col == 64) {
                int row = wm2*16 + qg + 8*(r >> 1);
                s_dnm[row] = acc2[j][r];
            }
        }
    __syncthreads();

    float invd0 = 1.0f / s_dnm[wm2*16 + qg];
    float invd1 = 1.0f / s_dnm[wm2*16 + qg + 8];
    float* ob = g_o + ((size_t)b*SEQ + n0)*DIM + hh*DH;
    #pragma unroll
    for (int j = 0; j < 5; j++)
        #pragma unroll
        for (int r = 0; r < 4; r++) {
            int col = wn2*40 + j*8 + qt*2 + (r & 1);
            if (col < 64) {
                int row = wm2*16 + qg + 8*(r >> 1);
                ob[(size_t)row*DIM + col] = acc2[j][r] * ((r >> 1) ? invd1 : invd0);
            }
        }
}

// ---------------- exp pass for kp ----------------
__global__ void __launch_bounds__(256) expk_kernel()
{
    int row = blockIdx.x * 8 + (threadIdx.x >> 5);
    int lane = threadIdx.x & 31;
    float dg = g_diag[row];
    float km = g_kmax;
    float* kp = g_kp + (size_t)row*MPAD;
    for (int c = lane; c < NB; c += 32)
        kp[c] = RATIO * (fast_exp(kp[c] - dg - km) + EPSF);
}

// ---------------- ctx: ctxExt[bh,m,0:65] = sum_n kp[n,m]*[v[n,:],1] (TF32 MMA, split-K) ----
__global__ void __launch_bounds__(256) ctx_kernel()
{
    __shared__ unsigned As[64*ASTR];
    __shared__ unsigned Bs[64*CSTR];
    const int tid = threadIdx.x, lane = tid & 31, warp = tid >> 5;
    const int qg = lane >> 2, qt = lane & 3;
    const int wm = warp >> 1, wn = warp & 1;
    const int f0 = blockIdx.x * 64, bh = blockIdx.y, b = bh >> 3, hh = bh & 7;
    const int nbase = blockIdx.z * (SEQ / SPLITK);

    if (tid < 64) {
        Bs[tid*CSTR + 64] = f2tf32(1.0f);
        #pragma unroll
        for (int c = 65; c < 80; c++) Bs[tid*CSTR + c] = 0u;
    }

    float acc[5][4];
    #pragma unroll
    for (int j = 0; j < 5; j++)
        #pragma unroll
        for (int r = 0; r < 4; r++) acc[j][r] = 0.f;

    for (int ch = 0; ch < SEQ/SPLITK; ch += 64) {
        __syncthreads();
        // kp tile transposed: As[feat][n]
        #pragma unroll
        for (int i = tid; i < 1024; i += 256) {
            int n = i >> 4, f4 = (i & 15) * 4;
            float4 v = *(const float4*)(g_kp + ((size_t)bh*SEQ + nbase + ch + n)*MPAD + f0 + f4);
            As[(f4+0)*ASTR + n] = f2tf32(v.x);
            As[(f4+1)*ASTR + n] = f2tf32(v.y);
            As[(f4+2)*ASTR + n] = f2tf32(v.z);
            As[(f4+3)*ASTR + n] = f2tf32(v.w);
        }
        // v tile: Bs[n][d]
        #pragma unroll
        for (int i = tid; i < 1024; i += 256) {
            int n = i >> 4, d4 = (i & 15) * 4;
            float4 v = *(const float4*)(g_v + ((size_t)b*SEQ + nbase + ch + n)*DIM + hh*DH + d4);
            Bs[n*CSTR + d4+0] = f2tf32(v.x);
            Bs[n*CSTR + d4+1] = f2tf32(v.y);
            Bs[n*CSTR + d4+2] = f2tf32(v.z);
            Bs[n*CSTR + d4+3] = f2tf32(v.w);
        }
        __syncthreads();
        #pragma unroll
        for (int kk = 0; kk < 64; kk += 8) {
            unsigned af[4], bf[5][2];
            const unsigned* ap = As + (wm*16 + qg)*ASTR + kk + qt;
            af[0] = ap[0];
            af[1] = ap[8*ASTR];
            af[2] = ap[4];
            af[3] = ap[8*ASTR + 4];
            #pragma unroll
            for (int j = 0; j < 5; j++) {
                const unsigned* bp = Bs + (kk + qt)*CSTR + wn*40 + j*8 + qg;
                bf[j][0] = bp[0];
                bf[j][1] = bp[4*CSTR];
            }
            #pragma unroll
            for (int j = 0; j < 5; j++)
                mma_tf32(acc[j], af, bf[j]);
        }
    }

    float* cb = g_ctx + (size_t)bh*MPAD*CTXW;
    #pragma unroll
    for (int j = 0; j < 5; j++)
        #pragma unroll
        for (int r = 0; r < 4; r++) {
            int row = wm*16 + qg + 8*(r >> 1);
            int col = wn*40 + j*8 + qt*2 + (r & 1);
            if (col < 65)
                atomicAdd(&cb[(f0 + row)*CTXW + col], acc[j][r]);
        }
}

// ---------------- final fc ----------------
__global__ void __launch_bounds__(256) fc_kernel(
    const float* __restrict__ x, const float* __restrict__ w,
    const float* __restrict__ bias, float* __restrict__ out)
{
    __shared__ float xs[8*DIM];
    int tid = threadIdx.x;
    int m0 = blockIdx.x * 8;
    for (int i = tid; i < 8*DIM/4; i += 256)
        ((float4*)xs)[i] = ((const float4*)(x + (size_t)m0*DIM))[i];
    __syncthreads();
    int r = tid >> 5, c = tid & 31;
    float acc = 0.f;
    const float* xr = &xs[r*DIM];
    #pragma unroll 8
    for (int k = 0; k < DIM; k++) acc += xr[k] * w[k*OUTD + c];
    out[(size_t)(m0 + r)*OUTD + c] = acc + bias[c];
}

// ---------------- host launcher ----------------
extern "C" void kernel_launch(void* const* d_in, const int* in_sizes, int n_in,
                              void* d_out, int out_size)
{
    (void)in_sizes; (void)n_in; (void)out_size;
    const float* src  = (const float*)d_in[0];
    const float* proj = (const float*)d_in[1];
    const float* ln1g = (const float*)d_in[2];
    const float* ln1b = (const float*)d_in[3];
    const float* Wq   = (const float*)d_in[4];
    const float* Wk   = (const float*)d_in[5];
    const float* Wv   = (const float*)d_in[6];
    const float* Wo   = (const float*)d_in[7];
    const float* bo   = (const float*)d_in[8];
    const float* ln2g = (const float*)d_in[9];
    const float* ln2b = (const float*)d_in[10];
    const float* W1   = (const float*)d_in[11];
    const float* b1   = (const float*)d_in[12];
    const float* W2   = (const float*)d_in[13];
    const float* b2   = (const float*)d_in[14];
    const float* fcw  = (const float*)d_in[15];
    const float* fcb  = (const float*)d_in[16];
    float* out = (float*)d_out;

    float *xp, *hp, *qb, *kb, *vb, *ob, *ffb;
    cudaGetSymbolAddress((void**)&xp,  g_x);
    cudaGetSymbolAddress((void**)&hp,  g_h);
    cudaGetSymbolAddress((void**)&qb,  g_q);
    cudaGetSymbolAddress((void**)&kb,  g_k);
    cudaGetSymbolAddress((void**)&vb,  g_v);
    cudaGetSymbolAddress((void**)&ob,  g_o);
    cudaGetSymbolAddress((void**)&ffb, g_ff);

    const int xk_smem = (64*ASTR + 64*BSTR)*4 + (64 + 256 + 64 + 8)*4;
    const int xq_smem = (64*ASTR + 64*BSTR + MPAD*CSTR)*4 + (64 + 256 + 64 + 8)*4;
    cudaFuncSetAttribute(xfeat_kernel<0>, cudaFuncAttributeMaxDynamicSharedMemorySize, xk_smem);
    cudaFuncSetAttribute(xfeat_kernel<1>, cudaFuncAttributeMaxDynamicSharedMemorySize, xq_smem);

    copy_src_kernel<<<(MROWS*DIM + 255)/256, 256>>>(src);

    dim3 gg(DIM/128, MROWS/128);
    dim3 gf(FFD/128, MROWS/128);
    dim3 xg(SEQ/64, BH);

    for (int L = 0; L < DEPTH; L++) {
        ln_kernel<<<MROWS, 128>>>(xp, ln1g + L*DIM, ln1b + L*DIM, hp);
        tgemm_kernel<0,0,0><<<gg, 256>>>(hp, Wq + (size_t)L*DIM*DIM, 0, 0, qb, MROWS, DIM, DIM);
        tgemm_kernel<0,0,0><<<gg, 256>>>(hp, Wk + (size_t)L*DIM*DIM, 0, 0, kb, MROWS, DIM, DIM);
        tgemm_kernel<0,0,0><<<gg, 256>>>(hp, Wv + (size_t)L*DIM*DIM, 0, 0, vb, MROWS, DIM, DIM);
        projt_kernel<<<(DH*MPAD + 255)/256, 256>>>(proj + (size_t)L*NB*DH);
        reset_kernel<<<(BH*MPAD*CTXW + 255)/256, 256>>>();
        xfeat_kernel<0><<<xg, 256, xk_smem>>>();
        expk_kernel<<<BH*SEQ/8, 256>>>();
        ctx_kernel<<<dim3(MPAD/64, BH, SPLITK), 256>>>();
        xfeat_kernel<1><<<xg, 256, xq_smem>>>();
        tgemm_kernel<1,1,0><<<gg, 256>>>(ob, Wo + (size_t)L*DIM*DIM, bo + L*DIM, xp, xp, MROWS, DIM, DIM);
        ln_kernel<<<MROWS, 128>>>(xp, ln2g + L*DIM, ln2b + L*DIM, hp);
        tgemm_kernel<1,0,1><<<gf, 256>>>(hp, W1 + (size_t)L*DIM*FFD, b1 + L*FFD, 0, ffb, MROWS, FFD, DIM);
        tgemm_kernel<1,1,0><<<gg, 256>>>(ffb, W2 + (size_t)L*FFD*DIM, b2 + L*DIM, xp, xp, MROWS, DIM, FFD);
    }
    fc_kernel<<<MROWS/8, 256>>>(xp, fcw, fcb, out);
}

// round 4
// speedup vs baseline: 3.5544x; 1.2676x over previous
#include <cuda_runtime.h>
#include <math.h>

#define DEPTH  6
#define DIM    512
#define HEADS  8
#define DH     64
#define NB     266
#define FFD    2048
#define OUTD   32
#define BATCH  4
#define SEQ    8192
#define MROWS  (BATCH*SEQ)   // 32768
#define BH     (BATCH*HEADS) // 32
#define MPAD   320
#define CTXW   80            // ctx row width (64 v + 1 ones + pad)
#define ASTR   68            // A-tile smem stride (attn kernels)
#define BSTR   332           // B/qp smem stride
#define CSTR   88            // ctx smem stride
#define EPSF   1e-4f
#define DN     0.3535533905932738f
#define RATIO  0.06131393394849658f
#define SPLITK 4
#define STG    4             // tgemm pipeline stages

// ---------------- scratch ----------------
__device__ __align__(256) float g_x[MROWS*DIM];
__device__ __align__(256) float g_h[MROWS*DIM];
__device__ __align__(256) float g_q[MROWS*DIM];
__device__ __align__(256) float g_k[MROWS*DIM];
__device__ __align__(256) float g_v[MROWS*DIM];
__device__ __align__(256) float g_o[MROWS*DIM];
__device__ __align__(256) float g_ff[MROWS*FFD];
__device__ __align__(256) float g_kpT[(size_t)BH*MPAD*SEQ];   // [bh][f][n] raw xp
__device__ __align__(256) float g_ctx[BH*MPAD*CTXW];
__device__ __align__(256) float g_diag[BH*SEQ];
__device__ __align__(256) unsigned g_projT[DH*MPAD];
__device__ float g_kmax;

// ---------------- helpers ----------------
__device__ __forceinline__ void atomicMaxF(float* addr, float val) {
    int old = __float_as_int(*addr);
    while (__int_as_float(old) < val) {
        int assumed = old;
        old = atomicCAS((int*)addr, assumed, __float_as_int(val));
        if (old == assumed) break;
    }
}

// fast exp on FMA pipe (avoids MUFU.EX2 wall)
__device__ __forceinline__ float fast_exp(float x) {
    float t = x * 1.4426950408889634f;
    t = fminf(fmaxf(t, -126.0f), 126.0f);
    float z = t + 12582912.0f;
    int n = __float_as_int(z) - 0x4B400000;
    float f = t - (z - 12582912.0f);
    float p = 1.33335581e-3f;
    p = fmaf(p, f, 9.61812911e-3f);
    p = fmaf(p, f, 5.55041087e-2f);
    p = fmaf(p, f, 2.40226507e-1f);
    p = fmaf(p, f, 6.93147181e-1f);
    p = fmaf(p, f, 1.0f);
    return p * __int_as_float((n + 127) << 23);
}

__device__ __forceinline__ float fast_rcp(float x) {
    float y = __int_as_float(0x7EF311C3 - __float_as_int(x));
    y = y * (2.0f - x * y);
    y = y * (2.0f - x * y);
    y = y * (2.0f - x * y);
    return y;
}

__device__ __forceinline__ float gelu_fast(float x) {
    float u = 0.7978845608028654f * (x + 0.044715f * x * x * x);
    u = fminf(fmaxf(u, -9.0f), 9.0f);
    float E = fast_exp(2.0f * u);
    float th = 1.0f - 2.0f * fast_rcp(E + 1.0f);
    return 0.5f * x * (1.0f + th);
}

__device__ __forceinline__ unsigned f2tf32(float x) {
    unsigned r;
    asm("cvt.rna.tf32.f32 %0, %1;" : "=r"(r) : "f"(x));
    return r;
}

__device__ __forceinline__ void mma_tf32(float (&d)[4], const unsigned (&a)[4], const unsigned (&b)[2]) {
    asm volatile(
        "mma.sync.aligned.m16n8k8.row.col.f32.tf32.tf32.f32 "
        "{%0,%1,%2,%3}, {%4,%5,%6,%7}, {%8,%9}, {%0,%1,%2,%3};\n"
        : "+f"(d[0]), "+f"(d[1]), "+f"(d[2]), "+f"(d[3])
        : "r"(a[0]), "r"(a[1]), "r"(a[2]), "r"(a[3]), "r"(b[0]), "r"(b[1]));
}

__device__ __forceinline__ void cp16(unsigned* s, const void* g) {
    unsigned saddr = (unsigned)__cvta_generic_to_shared(s);
    asm volatile("cp.async.cg.shared.global [%0], [%1], 16;\n" :: "r"(saddr), "l"(g));
}
__device__ __forceinline__ void cp_commit() { asm volatile("cp.async.commit_group;\n"); }
template<int N> __device__ __forceinline__ void cp_wait() {
    asm volatile("cp.async.wait_group %0;\n" :: "n"(N));
}

// ---------------- init / reset ----------------
__global__ void copy_src_kernel(const float* __restrict__ src) {
    int i = blockIdx.x * blockDim.x + threadIdx.x;
    if (i < MROWS*DIM) g_x[i] = src[i];
}

__global__ void reset_kernel() {
    int i = blockIdx.x * blockDim.x + threadIdx.x;
    if (i < BH*MPAD*CTXW) g_ctx[i] = 0.f;
    if (i == 0) g_kmax = __int_as_float(0xff800000);
}

__global__ void projt_kernel(const float* __restrict__ proj) {
    int i = blockIdx.x * blockDim.x + threadIdx.x;
    if (i < DH*MPAD) {
        int d = i / MPAD, f = i % MPAD;
        float v = (f < NB) ? proj[f*DH + d] : 0.f;
        g_projT[i] = f2tf32(v);
    }
}

// ---------------- LayerNorm ----------------
__global__ void __launch_bounds__(128) ln_kernel(
    const float* __restrict__ x, const float* __restrict__ g,
    const float* __restrict__ b, float* __restrict__ o)
{
    int row = blockIdx.x, tid = threadIdx.x, lane = tid & 31, w = tid >> 5;
    const float4 xv = ((const float4*)(x + (size_t)row*DIM))[tid];
    float s = xv.x + xv.y + xv.z + xv.w;
    float q = xv.x*xv.x + xv.y*xv.y + xv.z*xv.z + xv.w*xv.w;
    #pragma unroll
    for (int off = 16; off; off >>= 1) {
        s += __shfl_xor_sync(0xffffffffu, s, off);
        q += __shfl_xor_sync(0xffffffffu, q, off);
    }
    __shared__ float ss[4], sq[4];
    if (lane == 0) { ss[w] = s; sq[w] = q; }
    __syncthreads();
    float S = ss[0]+ss[1]+ss[2]+ss[3];
    float Q = sq[0]+sq[1]+sq[2]+sq[3];
    float mean = S * (1.0f/DIM);
    float var  = Q * (1.0f/DIM) - mean*mean;
    float inv  = rsqrtf(var + 1e-5f);
    float4 gv = ((const float4*)g)[tid];
    float4 bv = ((const float4*)b)[tid];
    float4 ov;
    ov.x = (xv.x - mean)*inv*gv.x + bv.x;
    ov.y = (xv.y - mean)*inv*gv.y + bv.y;
    ov.z = (xv.z - mean)*inv*gv.z + bv.z;
    ov.w = (xv.w - mean)*inv*gv.w + bv.w;
    ((float4*)(o + (size_t)row*DIM))[tid] = ov;
}

// ---------------- TF32 GEMM, cp.async 4-stage pipeline ----------------
// C[M,N] = [res +] epi(A[M,K]*W[K,N] [+bias]).  M%128==0, N%128==0, K%16==0.
// 128x128x16 CTA tile, 256 threads, warp tile 64x32. Raw fp32 bits as tf32.
template<int BIASF, int RESF, int GELUF>
__global__ void __launch_bounds__(256, 2) tgemm_kernel(
    const float* __restrict__ A, const float* __restrict__ W,
    const float* __restrict__ bias, const float* __restrict__ res,
    float* __restrict__ C, int M, int N, int K)
{
    extern __shared__ unsigned smu[];
    const int ASZ = 128*20, BSZ = 16*136;
    unsigned* As = smu;               // [STG][128][20]
    unsigned* Bs = smu + STG*ASZ;     // [STG][16][136]

    const int tid = threadIdx.x, lane = tid & 31, warp = tid >> 5;
    const int wm = warp >> 2, wn = warp & 3;
    const int qg = lane >> 2, qt = lane & 3;
    const float* Ab = A + (size_t)(blockIdx.y*128)*K;
    const float* Wb = W + blockIdx.x*128;

    // copy mapping
    const int ar = tid >> 2, ac = (tid & 3) * 4;
    const int br = tid >> 5, bc = (tid & 31) * 4;
    const int sa0 = ar*20 + ac, sa1 = (ar+64)*20 + ac;
    const int sb0 = br*136 + bc, sb1 = (br+8)*136 + bc;
    const float* ga0 = Ab + (size_t)ar*K + ac;
    const float* ga1 = Ab + (size_t)(ar+64)*K + ac;
    const float* gb0 = Wb + (size_t)br*N + bc;
    const float* gb1 = Wb + (size_t)(br+8)*N + bc;

    float acc[4][4][4];
    #pragma unroll
    for (int i = 0; i < 4; i++)
        #pragma unroll
        for (int j = 0; j < 4; j++)
            #pragma unroll
            for (int r = 0; r < 4; r++) acc[i][j][r] = 0.f;

    const int ntiles = K >> 4;

    #pragma unroll
    for (int s = 0; s < STG-1; s++) {
        unsigned* Ad = As + s*ASZ;
        unsigned* Bd = Bs + s*BSZ;
        cp16(Ad + sa0, ga0 + s*16);
        cp16(Ad + sa1, ga1 + s*16);
        cp16(Bd + sb0, gb0 + (size_t)(s*16)*N);
        cp16(Bd + sb1, gb1 + (size_t)(s*16)*N);
        cp_commit();
    }
    cp_wait<STG-2>();
    __syncthreads();

    #pragma unroll 1
    for (int kt = 0; kt < ntiles; kt++) {
        const int stg = kt & (STG-1);
        // issue stage kt+STG-1
        if (kt + STG-1 < ntiles) {
            const int ns = (kt + STG-1) & (STG-1);
            unsigned* Ad = As + ns*ASZ;
            unsigned* Bd = Bs + ns*BSZ;
            const int ko = (kt + STG-1) * 16;
            cp16(Ad + sa0, ga0 + ko);
            cp16(Ad + sa1, ga1 + ko);
            cp16(Bd + sb0, gb0 + (size_t)ko*N);
            cp16(Bd + sb1, gb1 + (size_t)ko*N);
        }
        cp_commit();

        const unsigned* At = As + stg*ASZ;
        const unsigned* Bt = Bs + stg*BSZ;
        #pragma unroll
        for (int kk = 0; kk < 16; kk += 8) {
            unsigned af[4][4], bf[4][2];
            #pragma unroll
            for (int i = 0; i < 4; i++) {
                const unsigned* ap = At + (wm*64 + i*16 + qg)*20 + kk + qt;
                af[i][0] = ap[0];
                af[i][1] = ap[8*20];
                af[i][2] = ap[4];
                af[i][3] = ap[8*20 + 4];
            }
            #pragma unroll
            for (int j = 0; j < 4; j++) {
                const unsigned* bp = Bt + (kk + qt)*136 + wn*32 + j*8 + qg;
                bf[j][0] = bp[0];
                bf[j][1] = bp[4*136];
            }
            #pragma unroll
            for (int i = 0; i < 4; i++)
                #pragma unroll
                for (int j = 0; j < 4; j++)
                    mma_tf32(acc[i][j], af[i], bf[j]);
        }
        cp_wait<STG-2>();
        __syncthreads();
    }

    const int row0 = blockIdx.y*128 + wm*64;
    const int col0 = blockIdx.x*128 + wn*32;
    #pragma unroll
    for (int i = 0; i < 4; i++) {
        #pragma unroll
        for (int j = 0; j < 4; j++) {
            int r = row0 + i*16 + qg;
            int c = col0 + j*8 + qt*2;
            float b0 = 0.f, b1 = 0.f;
            if (BIASF) { b0 = bias[c]; b1 = bias[c+1]; }
            float v0 = acc[i][j][0] + b0;
            float v1 = acc[i][j][1] + b1;
            float v2 = acc[i][j][2] + b0;
            float v3 = acc[i][j][3] + b1;
            if (GELUF) { v0 = gelu_fast(v0); v1 = gelu_fast(v1); v2 = gelu_fast(v2); v3 = gelu_fast(v3); }
            if (RESF) {
                const float2 r0v = *(const float2*)(res + (size_t)r*N + c);
                const float2 r1v = *(const float2*)(res + (size_t)(r+8)*N + c);
                v0 += r0v.x; v1 += r0v.y; v2 += r1v.x; v3 += r1v.y;
            }
            *(float2*)(C + (size_t)r*N + c)     = make_float2(v0, v1);
            *(float2*)(C + (size_t)(r+8)*N + c) = make_float2(v2, v3);
        }
    }
}

// ---------------- feature-map kernels (TF32 MMA) ----------------
// ISQ=0: k path — raw xp -> g_kpT (transposed, padded/masked), diag, blockmax->g_kmax
// ISQ=1: q path — xq MMA + rowmax + exp -> qp(smem) -> MMA with ctxExt -> g_o
template<int ISQ>
__global__ void __launch_bounds__(256) xfeat_kernel()
{
    extern __shared__ unsigned smu[];
    unsigned* As = smu;
    unsigned* Bs = As + 64*ASTR;
    unsigned* Cs = Bs + 64*BSTR;
    float* s_aux = (float*)(ISQ ? (Cs + MPAD*CSTR) : Cs);
    float* s_diag = s_aux;
    float* s_rmax = s_diag + 64;
    float* s_dnm  = s_rmax + 256;
    float* s_wm   = s_dnm + 64;

    const int tid = threadIdx.x, lane = tid & 31, warp = tid >> 5;
    const int qg = lane >> 2, qt = lane & 3;
    const int wm = warp >> 2, wn = warp & 3;
    const int bh = blockIdx.y, b = bh >> 3, hh = bh & 7;
    const int n0 = blockIdx.x * 64;
    const float* src = (ISQ ? g_q : g_k) + ((size_t)b*SEQ + n0)*DIM + hh*DH;

    #pragma unroll
    for (int i = tid; i < 64*16; i += 256) {
        int r = i >> 4, c4 = (i & 15) * 4;
        float4 v = *(const float4*)(src + (size_t)r*DIM + c4);
        As[r*ASTR + c4+0] = f2tf32(v.x*DN);
        As[r*ASTR + c4+1] = f2tf32(v.y*DN);
        As[r*ASTR + c4+2] = f2tf32(v.z*DN);
        As[r*ASTR + c4+3] = f2tf32(v.w*DN);
    }
    #pragma unroll
    for (int i = tid; i < 64*80; i += 256) {
        int r = i / 80, c4 = (i % 80) * 4;
        uint4 v = *(const uint4*)(g_projT + r*MPAD + c4);
        Bs[r*BSTR + c4+0] = v.x;
        Bs[r*BSTR + c4+1] = v.y;
        Bs[r*BSTR + c4+2] = v.z;
        Bs[r*BSTR + c4+3] = v.w;
    }
    if (ISQ) {
        const float* cb = g_ctx + (size_t)bh*MPAD*CTXW;
        #pragma unroll
        for (int i = tid; i < MPAD*20; i += 256) {
            int r = i / 20, c4 = (i % 20) * 4;
            float4 v = *(const float4*)(cb + r*CTXW + c4);
            Cs[r*CSTR + c4+0] = f2tf32(v.x);
            Cs[r*CSTR + c4+1] = f2tf32(v.y);
            Cs[r*CSTR + c4+2] = f2tf32(v.z);
            Cs[r*CSTR + c4+3] = f2tf32(v.w);
        }
    }
    __syncthreads();

    if (tid < 64) {
        float s = 0.f;
        #pragma unroll 16
        for (int d = 0; d < DH; d++) {
            float v = __uint_as_float(As[tid*ASTR + d]);
            s += v*v;
        }
        s = 0.5f * s;
        s_diag[tid] = s;
        if (!ISQ) g_diag[(size_t)bh*SEQ + n0 + tid] = s;
    }

    float acc1[2][10][4];
    #pragma unroll
    for (int i = 0; i < 2; i++)
        #pragma unroll
        for (int j = 0; j < 10; j++)
            #pragma unroll
            for (int r = 0; r < 4; r++) acc1[i][j][r] = 0.f;

    #pragma unroll
    for (int kk = 0; kk < 64; kk += 8) {
        unsigned af[2][4], bf[10][2];
        #pragma unroll
        for (int i = 0; i < 2; i++) {
            const unsigned* ap = As + (wm*32 + i*16 + qg)*ASTR + kk + qt;
            af[i][0] = ap[0];
            af[i][1] = ap[8*ASTR];
            af[i][2] = ap[4];
            af[i][3] = ap[8*ASTR + 4];
        }
        #pragma unroll
        for (int j = 0; j < 10; j++) {
            const unsigned* bp = Bs + (kk + qt)*BSTR + wn*80 + j*8 + qg;
            bf[j][0] = bp[0];
            bf[j][1] = bp[4*BSTR];
        }
        #pragma unroll
        for (int i = 0; i < 2; i++)
            #pragma unroll
            for (int j = 0; j < 10; j++)
                mma_tf32(acc1[i][j], af[i], bf[j]);
    }

    float* fBs = (float*)Bs;

    if (!ISQ) {
        float m = __int_as_float(0xff800000);
        #pragma unroll
        for (int i = 0; i < 2; i++)
            #pragma unroll
            for (int j = 0; j < 10; j++)
                #pragma unroll
                for (int r = 0; r < 4; r++) {
                    int col = wn*80 + j*8 + qt*2 + (r & 1);
                    if (col < NB) m = fmaxf(m, acc1[i][j][r]);
                }
        #pragma unroll
        for (int off = 16; off; off >>= 1) m = fmaxf(m, __shfl_xor_sync(0xffffffffu, m, off));
        if (lane == 0) s_wm[warp] = m;
        __syncthreads();
        if (tid == 0) {
            float mm = s_wm[0];
            #pragma unroll
            for (int i = 1; i < 8; i++) mm = fmaxf(mm, s_wm[i]);
            atomicMaxF(&g_kmax, mm);
        }
        // stage raw xp (masked) into fBs[n][f]
        #pragma unroll
        for (int i = 0; i < 2; i++)
            #pragma unroll
            for (int j = 0; j < 10; j++)
                #pragma unroll
                for (int r = 0; r < 4; r++) {
                    int row = wm*32 + i*16 + qg + 8*(r >> 1);
                    int col = wn*80 + j*8 + qt*2 + (r & 1);
                    fBs[row*BSTR + col] = (col < NB) ? acc1[i][j][r] : 0.f;
                }
        __syncthreads();
        // transposed copy to g_kpT[bh][f][n]
        #pragma unroll
        for (int i = tid; i < 64*80; i += 256) {
            int n = i & 63, f4 = (i >> 6) * 4;
            float4 v = *(const float4*)&fBs[n*BSTR + f4];
            float* dst = g_kpT + ((size_t)bh*MPAD + f4)*SEQ + n0 + n;
            dst[0]      = v.x;
            dst[SEQ]    = v.y;
            dst[2*SEQ]  = v.z;
            dst[3*SEQ]  = v.w;
        }
        return;
    }

    // ===== ISQ: rowmax =====
    #pragma unroll
    for (int i = 0; i < 2; i++) {
        #pragma unroll
        for (int h = 0; h < 2; h++) {
            float m = __int_as_float(0xff800000);
            #pragma unroll
            for (int j = 0; j < 10; j++) {
                #pragma unroll
                for (int rb = 0; rb < 2; rb++) {
                    int col = wn*80 + j*8 + qt*2 + rb;
                    if (col < NB) m = fmaxf(m, acc1[i][j][2*h + rb]);
                }
            }
            m = fmaxf(m, __shfl_xor_sync(0xffffffffu, m, 1));
            m = fmaxf(m, __shfl_xor_sync(0xffffffffu, m, 2));
            if (qt == 0) s_rmax[(wm*32 + i*16 + qg + 8*h)*4 + wn] = m;
        }
    }
    __syncthreads();

    float sub[2][2];
    #pragma unroll
    for (int i = 0; i < 2; i++)
        #pragma unroll
        for (int h = 0; h < 2; h++) {
            int row = wm*32 + i*16 + qg + 8*h;
            float m = fmaxf(fmaxf(s_rmax[row*4+0], s_rmax[row*4+1]),
                            fmaxf(s_rmax[row*4+2], s_rmax[row*4+3]));
            sub[i][h] = m + s_diag[row];
        }
    #pragma unroll
    for (int i = 0; i < 2; i++)
        #pragma unroll
        for (int j = 0; j < 10; j++)
            #pragma unroll
            for (int r = 0; r < 4; r++) {
                int row = wm*32 + i*16 + qg + 8*(r >> 1);
                int col = wn*80 + j*8 + qt*2 + (r & 1);
                float v = 0.f;
                if (col < NB) v = RATIO * (fast_exp(acc1[i][j][r] - sub[i][r >> 1]) + EPSF);
                Bs[row*BSTR + col] = f2tf32(v);
            }
    __syncthreads();

    const int wm2 = warp >> 1, wn2 = warp & 1;
    float acc2[5][4];
    #pragma unroll
    for (int j = 0; j < 5; j++)
        #pragma unroll
        for (int r = 0; r < 4; r++) acc2[j][r] = 0.f;

    #pragma unroll 4
    for (int kk = 0; kk < MPAD; kk += 8) {
        unsigned af[4], bf[5][2];
        const unsigned* ap = Bs + (wm2*16 + qg)*BSTR + kk + qt;
        af[0] = ap[0];
        af[1] = ap[8*BSTR];
        af[2] = ap[4];
        af[3] = ap[8*BSTR + 4];
        #pragma unroll
        for (int j = 0; j < 5; j++) {
            const unsigned* bp = Cs + (kk + qt)*CSTR + wn2*40 + j*8 + qg;
            bf[j][0] = bp[0];
            bf[j][1] = bp[4*CSTR];
        }
        #pragma unroll
        for (int j = 0; j < 5; j++)
            mma_tf32(acc2[j], af, bf[j]);
    }

    #pragma unroll
    for (int j = 0; j < 5; j++)
        #pragma unroll
        for (int r = 0; r < 4; r++) {
            int col = wn2*40 + j*8 + qt*2 + (r & 1);
            if (col == 64) {
                int row = wm2*16 + qg + 8*(r >> 1);
                s_dnm[row] = acc2[j][r];
            }
        }
    __syncthreads();

    float invd0 = 1.0f / s_dnm[wm2*16 + qg];
    float invd1 = 1.0f / s_dnm[wm2*16 + qg + 8];
    float* ob = g_o + ((size_t)b*SEQ + n0)*DIM + hh*DH;
    #pragma unroll
    for (int j = 0; j < 5; j++)
        #pragma unroll
        for (int r = 0; r < 4; r++) {
            int col = wn2*40 + j*8 + qt*2 + (r & 1);
            if (col < 64) {
                int row = wm2*16 + qg + 8*(r >> 1);
                ob[(size_t)row*DIM + col] = acc2[j][r] * ((r >> 1) ? invd1 : invd0);
            }
        }
}

// ---------------- ctx: ctxExt[bh,f,0:65] = sum_n kp[f,n]*[v[n,:],1]  (exp fused) ----------------
__global__ void __launch_bounds__(256) ctx_kernel()
{
    __shared__ unsigned As[64*ASTR];   // [f][n]
    __shared__ unsigned Bs[64*CSTR];   // [n][d + ones]
    const int tid = threadIdx.x, lane = tid & 31, warp = tid >> 5;
    const int qg = lane >> 2, qt = lane & 3;
    const int wm = warp >> 1, wn = warp & 1;
    const int f0 = blockIdx.x * 64, bh = blockIdx.y, b = bh >> 3, hh = bh & 7;
    const int nbase = blockIdx.z * (SEQ / SPLITK);
    const float km = g_kmax;

    if (tid < 64) {
        Bs[tid*CSTR + 64] = 0x3f800000u;   // 1.0f
        #pragma unroll
        for (int c = 65; c < 80; c++) Bs[tid*CSTR + c] = 0u;
    }

    float acc[5][4];
    #pragma unroll
    for (int j = 0; j < 5; j++)
        #pragma unroll
        for (int r = 0; r < 4; r++) acc[j][r] = 0.f;

    for (int ch = 0; ch < SEQ/SPLITK; ch += 64) {
        __syncthreads();
        const int n0 = nbase + ch;
        // A: raw xp -> exp fused
        #pragma unroll
        for (int i = tid; i < 1024; i += 256) {
            int f = i >> 4, n4 = (i & 15) * 4;
            float4 v  = *(const float4*)(g_kpT + ((size_t)bh*MPAD + f0 + f)*SEQ + n0 + n4);
            float4 dg = *(const float4*)(g_diag + (size_t)bh*SEQ + n0 + n4);
            unsigned* ap = As + f*ASTR + n4;
            ap[0] = __float_as_uint(RATIO * (fast_exp(v.x - dg.x - km) + EPSF));
            ap[1] = __float_as_uint(RATIO * (fast_exp(v.y - dg.y - km) + EPSF));
            ap[2] = __float_as_uint(RATIO * (fast_exp(v.z - dg.z - km) + EPSF));
            ap[3] = __float_as_uint(RATIO * (fast_exp(v.w - dg.w - km) + EPSF));
        }
        // B: v raw bits
        #pragma unroll
        for (int i = tid; i < 1024; i += 256) {
            int n = i >> 4, d4 = (i & 15) * 4;
            float4 v = *(const float4*)(g_v + ((size_t)b*SEQ + n0 + n)*DIM + hh*DH + d4);
            unsigned* bp = Bs + n*CSTR + d4;
            bp[0] = __float_as_uint(v.x);
            bp[1] = __float_as_uint(v.y);
            bp[2] = __float_as_uint(v.z);
            bp[3] = __float_as_uint(v.w);
        }
        __syncthreads();
        #pragma unroll
        for (int kk = 0; kk < 64; kk += 8) {
            unsigned af[4], bf[5][2];
            const unsigned* ap = As + (wm*16 + qg)*ASTR + kk + qt;
            af[0] = ap[0];
            af[1] = ap[8*ASTR];
            af[2] = ap[4];
            af[3] = ap[8*ASTR + 4];
            #pragma unroll
            for (int j = 0; j < 5; j++) {
                const unsigned* bp = Bs + (kk + qt)*CSTR + wn*40 + j*8 + qg;
                bf[j][0] = bp[0];
                bf[j][1] = bp[4*CSTR];
            }
            #pragma unroll
            for (int j = 0; j < 5; j++)
                mma_tf32(acc[j], af, bf[j]);
        }
    }

    float* cb = g_ctx + (size_t)bh*MPAD*CTXW;
    #pragma unroll
    for (int j = 0; j < 5; j++)
        #pragma unroll
        for (int r = 0; r < 4; r++) {
            int row = wm*16 + qg + 8*(r >> 1);
            int col = wn*40 + j*8 + qt*2 + (r & 1);
            if (col < 65)
                atomicAdd(&cb[(f0 + row)*CTXW + col], acc[j][r]);
        }
}

// ---------------- final fc ----------------
__global__ void __launch_bounds__(256) fc_kernel(
    const float* __restrict__ x, const float* __restrict__ w,
    const float* __restrict__ bias, float* __restrict__ out)
{
    __shared__ float xs[8*DIM];
    int tid = threadIdx.x;
    int m0 = blockIdx.x * 8;
    for (int i = tid; i < 8*DIM/4; i += 256)
        ((float4*)xs)[i] = ((const float4*)(x + (size_t)m0*DIM))[i];
    __syncthreads();
    int r = tid >> 5, c = tid & 31;
    float acc = 0.f;
    const float* xr = &xs[r*DIM];
    #pragma unroll 8
    for (int k = 0; k < DIM; k++) acc += xr[k] * w[k*OUTD + c];
    out[(size_t)(m0 + r)*OUTD + c] = acc + bias[c];
}

// ---------------- host launcher ----------------
extern "C" void kernel_launch(void* const* d_in, const int* in_sizes, int n_in,
                              void* d_out, int out_size)
{
    (void)in_sizes; (void)n_in; (void)out_size;
    const float* src  = (const float*)d_in[0];
    const float* proj = (const float*)d_in[1];
    const float* ln1g = (const float*)d_in[2];
    const float* ln1b = (const float*)d_in[3];
    const float* Wq   = (const float*)d_in[4];
    const float* Wk   = (const float*)d_in[5];
    const float* Wv   = (const float*)d_in[6];
    const float* Wo   = (const float*)d_in[7];
    const float* bo   = (const float*)d_in[8];
    const float* ln2g = (const float*)d_in[9];
    const float* ln2b = (const float*)d_in[10];
    const float* W1   = (const float*)d_in[11];
    const float* b1   = (const float*)d_in[12];
    const float* W2   = (const float*)d_in[13];
    const float* b2   = (const float*)d_in[14];
    const float* fcw  = (const float*)d_in[15];
    const float* fcb  = (const float*)d_in[16];
    float* out = (float*)d_out;

    float *xp, *hp, *qb, *kb, *vb, *ob, *ffb;
    cudaGetSymbolAddress((void**)&xp,  g_x);
    cudaGetSymbolAddress((void**)&hp,  g_h);
    cudaGetSymbolAddress((void**)&qb,  g_q);
    cudaGetSymbolAddress((void**)&kb,  g_k);
    cudaGetSymbolAddress((void**)&vb,  g_v);
    cudaGetSymbolAddress((void**)&ob,  g_o);
    cudaGetSymbolAddress((void**)&ffb, g_ff);

    const int gemm_smem = STG*(128*20 + 16*136)*4;  // 75776
    cudaFuncSetAttribute(tgemm_kernel<0,0,0>, cudaFuncAttributeMaxDynamicSharedMemorySize, gemm_smem);
    cudaFuncSetAttribute(tgemm_kernel<1,1,0>, cudaFuncAttributeMaxDynamicSharedMemorySize, gemm_smem);
    cudaFuncSetAttribute(tgemm_kernel<1,0,1>, cudaFuncAttributeMaxDynamicSharedMemorySize, gemm_smem);

    const int xk_smem = (64*ASTR + 64*BSTR)*4 + (64 + 256 + 64 + 8)*4;
    const int xq_smem = (64*ASTR + 64*BSTR + MPAD*CSTR)*4 + (64 + 256 + 64 + 8)*4;
    cudaFuncSetAttribute(xfeat_kernel<0>, cudaFuncAttributeMaxDynamicSharedMemorySize, xk_smem);
    cudaFuncSetAttribute(xfeat_kernel<1>, cudaFuncAttributeMaxDynamicSharedMemorySize, xq_smem);

    copy_src_kernel<<<(MROWS*DIM + 255)/256, 256>>>(src);

    dim3 gg(DIM/128, MROWS/128);
    dim3 gf(FFD/128, MROWS/128);
    dim3 xg(SEQ/64, BH);

    for (int L = 0; L < DEPTH; L++) {
        ln_kernel<<<MROWS, 128>>>(xp, ln1g + L*DIM, ln1b + L*DIM, hp);
        tgemm_kernel<0,0,0><<<gg, 256, gemm_smem>>>(hp, Wq + (size_t)L*DIM*DIM, 0, 0, qb, MROWS, DIM, DIM);
        tgemm_kernel<0,0,0><<<gg, 256, gemm_smem>>>(hp, Wk + (size_t)L*DIM*DIM, 0, 0, kb, MROWS, DIM, DIM);
        tgemm_kernel<0,0,0><<<gg, 256, gemm_smem>>>(hp, Wv + (size_t)L*DIM*DIM, 0, 0, vb, MROWS, DIM, DIM);
        projt_kernel<<<(DH*MPAD + 255)/256, 256>>>(proj + (size_t)L*NB*DH);
        reset_kernel<<<(BH*MPAD*CTXW + 255)/256, 256>>>();
        xfeat_kernel<0><<<xg, 256, xk_smem>>>();
        ctx_kernel<<<dim3(MPAD/64, BH, SPLITK), 256>>>();
        xfeat_kernel<1><<<xg, 256, xq_smem>>>();
        tgemm_kernel<1,1,0><<<gg, 256, gemm_smem>>>(ob, Wo + (size_t)L*DIM*DIM, bo + L*DIM, xp, xp, MROWS, DIM, DIM);
        ln_kernel<<<MROWS, 128>>>(xp, ln2g + L*DIM, ln2b + L*DIM, hp);
        tgemm_kernel<1,0,1><<<gf, 256, gemm_smem>>>(hp, W1 + (size_t)L*DIM*FFD, b1 + L*FFD, 0, ffb, MROWS, FFD, DIM);
        tgemm_kernel<1,1,0><<<gg, 256, gemm_smem>>>(ffb, W2 + (size_t)L*FFD*DIM, b2 + L*DIM, xp, xp, MROWS, DIM, FFD);
    }
    fc_kernel<<<MROWS/8, 256>>>(xp, fcw, fcb, out);
}